// round 5
// baseline (speedup 1.0000x reference)
#include <cuda_runtime.h>
#include <cstdint>

#define B_   2
#define S_   2048
#define DIM_ 1024
#define NH_  8
#define MROWS (B_*S_)           // 4096
#define QD   128
#define VD   256
#define NT_  (S_/64)            // 32 key tiles

// ---------------- scratch ----------------
__device__ float g_cq  [MROWS*128];
__device__ float g_ckv [MROWS*192];
__device__ float g_q   [MROWS*1024];
__device__ float g_kv  [(size_t)MROWS*2560];
__device__ float g_Qs  [(size_t)B_*NH_*S_*QD];
__device__ float g_Ks  [(size_t)B_*NH_*S_*QD];
__device__ float g_Vs  [(size_t)B_*NH_*S_*VD];
__device__ float g_attn[(size_t)MROWS*2048];
__device__ float g_wuq [128*1024];
__device__ float g_wukv[128*2560];
__device__ float g_wo  [(size_t)2048*1024];

// ---------------- helpers ----------------
__device__ __forceinline__ float f2tf(float x) {
    uint32_t u;
    asm("cvt.rna.tf32.f32 %0, %1;" : "=r"(u) : "f"(x));
    return __uint_as_float(u);
}

__device__ __forceinline__ void mma8(float& d0, float& d1, float& d2, float& d3,
                                     float a0, float a1, float a2, float a3,
                                     float b0, float b1)
{
    uint32_t A0 = __float_as_uint(a0), A1 = __float_as_uint(a1);
    uint32_t A2 = __float_as_uint(a2), A3 = __float_as_uint(a3);
    uint32_t B0 = __float_as_uint(b0), B1 = __float_as_uint(b1);
    asm volatile(
        "mma.sync.aligned.m16n8k8.row.col.f32.tf32.tf32.f32 "
        "{%0,%1,%2,%3},{%4,%5,%6,%7},{%8,%9},{%0,%1,%2,%3};\n"
        : "+f"(d0), "+f"(d1), "+f"(d2), "+f"(d3)
        : "r"(A0), "r"(A1), "r"(A2), "r"(A3), "r"(B0), "r"(B1));
}

__device__ __forceinline__ void cp16(float* dst_smem, const float* src_gmem) {
    uint32_t d = (uint32_t)__cvta_generic_to_shared(dst_smem);
    asm volatile("cp.async.cg.shared.global [%0], [%1], 16;" :: "r"(d), "l"(src_gmem));
}
__device__ __forceinline__ void cp_commit() {
    asm volatile("cp.async.commit_group;");
}
template<int N> __device__ __forceinline__ void cp_wait() {
    asm volatile("cp.async.wait_group %0;" :: "n"(N));
}

// ---------------- weight pre-round to tf32 ----------------
__global__ void tfround_k(const float* __restrict__ src, float* __restrict__ dst, int n)
{
    int i = (blockIdx.x * blockDim.x + threadIdx.x) * 4;
    if (i < n) {
        float4 v = *(const float4*)&src[i];
        v.x = f2tf(v.x); v.y = f2tf(v.y); v.z = f2tf(v.z); v.w = f2tf(v.w);
        *(float4*)&dst[i] = v;
    }
}

// ---------------- fp32 SGEMM (the two down-projections) ----------------
__global__ void __launch_bounds__(256) sgemm_bias(
    const float* __restrict__ A, const float* __restrict__ Bm,
    const float* __restrict__ bias, float* __restrict__ C,
    int M, int N, int K, int lda)
{
    __shared__ float As[8][128];
    __shared__ float Bs[8][128];

    const int tid = threadIdx.x;
    const int tx  = tid & 15;
    const int ty  = tid >> 4;
    const int bm  = blockIdx.y * 128;
    const int bn  = blockIdx.x * 128;

    const int arow = tid >> 1, acol = (tid & 1) << 2;
    const int brow = tid >> 5, bcol = (tid & 31) << 2;

    float acc[8][8];
#pragma unroll
    for (int i = 0; i < 8; i++)
#pragma unroll
        for (int j = 0; j < 8; j++) acc[i][j] = 0.f;

    for (int k0 = 0; k0 < K; k0 += 8) {
        float4 av = *(const float4*)&A[(size_t)(bm + arow) * lda + k0 + acol];
        float4 bv = make_float4(0.f, 0.f, 0.f, 0.f);
        if (bn + bcol < N)
            bv = *(const float4*)&Bm[(size_t)(k0 + brow) * N + bn + bcol];

        __syncthreads();
        As[acol + 0][arow] = av.x;
        As[acol + 1][arow] = av.y;
        As[acol + 2][arow] = av.z;
        As[acol + 3][arow] = av.w;
        *(float4*)&Bs[brow][bcol] = bv;
        __syncthreads();

#pragma unroll
        for (int kk = 0; kk < 8; kk++) {
            float4 a0 = *(const float4*)&As[kk][ty * 4];
            float4 a1 = *(const float4*)&As[kk][64 + ty * 4];
            float4 b0 = *(const float4*)&Bs[kk][tx * 4];
            float4 b1 = *(const float4*)&Bs[kk][64 + tx * 4];
            float a[8] = {a0.x, a0.y, a0.z, a0.w, a1.x, a1.y, a1.z, a1.w};
            float b[8] = {b0.x, b0.y, b0.z, b0.w, b1.x, b1.y, b1.z, b1.w};
#pragma unroll
            for (int i = 0; i < 8; i++)
#pragma unroll
                for (int j = 0; j < 8; j++)
                    acc[i][j] += a[i] * b[j];
        }
    }

#pragma unroll
    for (int i = 0; i < 8; i++) {
        int row = bm + ((i < 4) ? (ty * 4 + i) : (64 + ty * 4 + i - 4));
#pragma unroll
        for (int j = 0; j < 8; j++) {
            int col = bn + ((j < 4) ? (tx * 4 + j) : (64 + tx * 4 + j - 4));
            if (col < N)
                C[(size_t)row * N + col] = acc[i][j] + bias[col];
        }
    }
}

// ---------------- tf32 GEMM, cp.async double-buffered ----------------
// Inputs MUST be pre-rounded to tf32. N must be a multiple of 128, K of 16.
__global__ void __launch_bounds__(256) gemm_tf32(
    const float* __restrict__ A, const float* __restrict__ Bm,
    const float* __restrict__ bias, float* __restrict__ C,
    int M, int N, int K, int lda)
{
    __shared__ float As[2][128 * 20];   // [row*20 + k]
    __shared__ float Bs[2][16 * 136];   // [k*136 + col]

    const int tid  = threadIdx.x;
    const int wid  = tid >> 5;
    const int lane = tid & 31;
    const int bm   = blockIdx.y * 128;
    const int bn   = blockIdx.x * 128;
    const int wm   = (wid >> 2) * 64;
    const int wn   = (wid & 3) * 32;
    const int r    = lane >> 2;
    const int c    = lane & 3;

    const int ar = tid >> 1, ac = (tid & 1) << 3;   // A: row, 2 chunks at ac, ac+4
    const int br = tid >> 4, bc = (tid & 15) << 3;  // B: row, 2 chunks at bc, bc+4

    float acc[4][4][4];
#pragma unroll
    for (int i = 0; i < 4; i++)
#pragma unroll
        for (int j = 0; j < 4; j++)
#pragma unroll
            for (int k = 0; k < 4; k++) acc[i][j][k] = 0.f;

    const int ns = K >> 4;

    // prologue
    {
        const float* ga = &A[(size_t)(bm + ar) * lda + ac];
        cp16(&As[0][ar * 20 + ac], ga);
        cp16(&As[0][ar * 20 + ac + 4], ga + 4);
        const float* gb = &Bm[(size_t)br * N + bn + bc];
        cp16(&Bs[0][br * 136 + bc], gb);
        cp16(&Bs[0][br * 136 + bc + 4], gb + 4);
        cp_commit();
    }

    for (int s = 0; s < ns; s++) {
        if (s + 1 < ns) {
            const int k0 = (s + 1) << 4, nb = (s + 1) & 1;
            const float* ga = &A[(size_t)(bm + ar) * lda + k0 + ac];
            cp16(&As[nb][ar * 20 + ac], ga);
            cp16(&As[nb][ar * 20 + ac + 4], ga + 4);
            const float* gb = &Bm[(size_t)(k0 + br) * N + bn + bc];
            cp16(&Bs[nb][br * 136 + bc], gb);
            cp16(&Bs[nb][br * 136 + bc + 4], gb + 4);
            cp_commit();
            cp_wait<1>();
        } else {
            cp_wait<0>();
        }
        __syncthreads();

        const float* as = As[s & 1];
        const float* bs = Bs[s & 1];
#pragma unroll
        for (int kk = 0; kk < 16; kk += 8) {
            float a[4][4], b[4][2];
#pragma unroll
            for (int mi = 0; mi < 4; mi++) {
                int row = wm + 16 * mi;
                a[mi][0] = as[(row + r) * 20 + kk + c];
                a[mi][1] = as[(row + r + 8) * 20 + kk + c];
                a[mi][2] = as[(row + r) * 20 + kk + c + 4];
                a[mi][3] = as[(row + r + 8) * 20 + kk + c + 4];
            }
#pragma unroll
            for (int ni = 0; ni < 4; ni++) {
                int col = wn + 8 * ni + r;
                b[ni][0] = bs[(kk + c) * 136 + col];
                b[ni][1] = bs[(kk + c + 4) * 136 + col];
            }
#pragma unroll
            for (int mi = 0; mi < 4; mi++)
#pragma unroll
                for (int ni = 0; ni < 4; ni++)
                    mma8(acc[mi][ni][0], acc[mi][ni][1], acc[mi][ni][2], acc[mi][ni][3],
                         a[mi][0], a[mi][1], a[mi][2], a[mi][3], b[ni][0], b[ni][1]);
        }
        __syncthreads();
    }

#pragma unroll
    for (int mi = 0; mi < 4; mi++) {
        int row0 = bm + wm + 16 * mi + r;
#pragma unroll
        for (int ni = 0; ni < 4; ni++) {
            int col0 = bn + wn + 8 * ni + 2 * c;
            C[(size_t)row0 * N + col0]           = acc[mi][ni][0] + bias[col0];
            C[(size_t)row0 * N + col0 + 1]       = acc[mi][ni][1] + bias[col0 + 1];
            C[(size_t)(row0 + 8) * N + col0]     = acc[mi][ni][2] + bias[col0];
            C[(size_t)(row0 + 8) * N + col0 + 1] = acc[mi][ni][3] + bias[col0 + 1];
        }
    }
}

// ---------------- small kernels (now emit tf32-rounded values) ----------------
__global__ void rmsnorm_kernel(float* __restrict__ buf, const float* __restrict__ w,
                               int stride)
{
    const int row = blockIdx.x;
    const int tid = threadIdx.x;
    float v = buf[(size_t)row * stride + tid];
    float s = v * v;
#pragma unroll
    for (int o = 16; o; o >>= 1) s += __shfl_xor_sync(0xffffffffu, s, o);
    __shared__ float ws[4];
    if ((tid & 31) == 0) ws[tid >> 5] = s;
    __syncthreads();
    float tot = ws[0] + ws[1] + ws[2] + ws[3];
    float rr = rsqrtf(tot / (float)blockDim.x + 1e-8f);
    buf[(size_t)row * stride + tid] = f2tf(w[tid] * v * rr);
}

__global__ void rope_kernel(float* __restrict__ buf, const int* __restrict__ pos,
                            int stride, int col_off, int hd)
{
    const int row = blockIdx.x;
    const int tid = threadIdx.x;
    const int half = hd >> 1;
    const int h = tid / half, i = tid % half;
    float p = (float)pos[row];
    float freq = powf(10000.0f, -2.0f * (float)i / (float)hd);
    float ang = p * freq;
    float sn, cs;
    sincosf(ang, &sn, &cs);
    size_t base = (size_t)row * stride + col_off + h * hd + 2 * i;
    float xe = buf[base], xo = buf[base + 1];
    buf[base]     = f2tf(xe * cs - xo * sn);
    buf[base + 1] = f2tf(xe * sn + xo * cs);
}

// repack into [b,h,s,d]; Q pre-scaled by 1/sqrt(128); everything tf32-rounded
__global__ void repack_kernel(const float* __restrict__ q, const float* __restrict__ kv,
                              const float* __restrict__ ckv,
                              float* __restrict__ Qo, float* __restrict__ Ko,
                              float* __restrict__ Vo)
{
    const int bhs = blockIdx.x;
    const int d   = threadIdx.x;
    const int s   = bhs & (S_ - 1);
    const int bh  = bhs >> 11;
    const int h   = bh & 7;
    const int b   = bh >> 3;
    const size_t row = (size_t)b * S_ + s;
    const size_t o128 = (size_t)bhs * 128, o256 = (size_t)bhs * 256;
    const float scale = 0.08838834764831845f;

    float qv = (d < 96) ? q[row * 1024 + h * 96 + d]
                        : q[row * 1024 + 768 + h * 32 + (d - 96)];
    Qo[o128 + d] = f2tf(qv * scale);
    Ko[o128 + d] = f2tf((d < 64) ? kv[row * 2560 + h * 64 + d]
                                 : ckv[row * 192 + 128 + (d - 64)]);
    Vo[o256 + d]       = f2tf(kv[row * 2560 + 512 + (size_t)h * 256 + d]);
    Vo[o256 + 128 + d] = f2tf(kv[row * 2560 + 512 + (size_t)h * 256 + 128 + d]);
}

// ---------------- tf32 flash attention, cp.async pipelined ----------------
// BM=64 q-rows, BN=64 keys. 8 warps: wm=wid>>1 rows, wn=wid&1.
// K double-buffered (hidden under previous PV); V single buffer (hidden under S+softmax).
#define SQ_STRIDE 132
#define SV_STRIDE 264
#define SP_STRIDE 68

__global__ void __launch_bounds__(256) flash_tf32(
    const float* __restrict__ Q, const float* __restrict__ K,
    const float* __restrict__ V, float* __restrict__ O)
{
    extern __shared__ float sm[];
    float* sQ  = sm;                        // 64*132
    float* sK  = sQ + 64 * SQ_STRIDE;       // 2 * 64*132
    float* sV  = sK + 2 * 64 * SQ_STRIDE;   // 64*264
    float* sP  = sV + 64 * SV_STRIDE;       // 64*68
    float* rMax = sP + 64 * SP_STRIDE;      // 2*64
    float* rSum = rMax + 128;               // 2*64

    const int tid  = threadIdx.x;
    const int wid  = tid >> 5;
    const int lane = tid & 31;
    const int wm   = wid >> 1;
    const int wn   = wid & 1;
    const int r    = lane >> 2;
    const int c    = lane & 3;
    const int bh   = blockIdx.y;
    const int qt   = blockIdx.x;

    // load maps for cp.async (4 threads per row)
    const int lrow = tid >> 2;
    const int kcol = (tid & 3) << 5;    // 32 floats -> 8 chunks
    const int vcol = (tid & 3) << 6;    // 64 floats -> 16 chunks

    const float* Kbh = K + (size_t)bh * S_ * QD;
    const float* Vbh = V + (size_t)bh * S_ * VD;

    // Q tile (already scaled + tf32-rounded)
    const float* Qg = Q + ((size_t)bh * S_ + qt * 64) * QD;
    for (int i = tid; i < 64 * 32; i += 256) {
        int row = i >> 5, col = (i & 31) << 2;
        *(float4*)&sQ[row * SQ_STRIDE + col] = *(const float4*)&Qg[row * QD + col];
    }

    float o[16][4];
#pragma unroll
    for (int i = 0; i < 16; i++)
#pragma unroll
        for (int j = 0; j < 4; j++) o[i][j] = 0.f;
    float m0 = -1e30f, m1 = -1e30f, l0 = 0.f, l1 = 0.f;

    const int row0 = 16 * wm + r;
    const int row1 = row0 + 8;

    // prologue: K(0)
    {
        const float* g = Kbh + (size_t)lrow * QD + kcol;
        float* d = &sK[lrow * SQ_STRIDE + kcol];
#pragma unroll
        for (int j = 0; j < 8; j++) cp16(d + 4 * j, g + 4 * j);
        cp_commit();
    }

    for (int kt = 0; kt < NT_; kt++) {
        // issue V(kt)
        {
            const float* g = Vbh + ((size_t)kt * 64 + lrow) * VD + vcol;
            float* d = &sV[lrow * SV_STRIDE + vcol];
#pragma unroll
            for (int j = 0; j < 16; j++) cp16(d + 4 * j, g + 4 * j);
            cp_commit();
        }
        // issue K(kt+1)
        if (kt + 1 < NT_) {
            const float* g = Kbh + ((size_t)(kt + 1) * 64 + lrow) * QD + kcol;
            float* d = &sK[((kt + 1) & 1) * 64 * SQ_STRIDE + lrow * SQ_STRIDE + kcol];
#pragma unroll
            for (int j = 0; j < 8; j++) cp16(d + 4 * j, g + 4 * j);
            cp_commit();
            cp_wait<2>();     // K(kt) done
        } else {
            cp_wait<1>();     // K(kt) done
        }
        __syncthreads();

        const float* sKb = sK + (kt & 1) * 64 * SQ_STRIDE;

        // ---- S = Q @ K^T (warp: 16 x 32) ----
        float s[4][4];
#pragma unroll
        for (int ni = 0; ni < 4; ni++)
#pragma unroll
            for (int j = 0; j < 4; j++) s[ni][j] = 0.f;

#pragma unroll
        for (int kk = 0; kk < 128; kk += 8) {
            float a0 = sQ[row0 * SQ_STRIDE + kk + c];
            float a1 = sQ[row1 * SQ_STRIDE + kk + c];
            float a2 = sQ[row0 * SQ_STRIDE + kk + c + 4];
            float a3 = sQ[row1 * SQ_STRIDE + kk + c + 4];
#pragma unroll
            for (int ni = 0; ni < 4; ni++) {
                int key = 32 * wn + 8 * ni + r;
                float b0 = sKb[key * SQ_STRIDE + kk + c];
                float b1 = sKb[key * SQ_STRIDE + kk + c + 4];
                mma8(s[ni][0], s[ni][1], s[ni][2], s[ni][3], a0, a1, a2, a3, b0, b1);
            }
        }

        // ---- online softmax ----
        float tmax0 = -1e30f, tmax1 = -1e30f;
#pragma unroll
        for (int ni = 0; ni < 4; ni++) {
            tmax0 = fmaxf(tmax0, fmaxf(s[ni][0], s[ni][1]));
            tmax1 = fmaxf(tmax1, fmaxf(s[ni][2], s[ni][3]));
        }
        tmax0 = fmaxf(tmax0, __shfl_xor_sync(0xffffffffu, tmax0, 1));
        tmax0 = fmaxf(tmax0, __shfl_xor_sync(0xffffffffu, tmax0, 2));
        tmax1 = fmaxf(tmax1, __shfl_xor_sync(0xffffffffu, tmax1, 1));
        tmax1 = fmaxf(tmax1, __shfl_xor_sync(0xffffffffu, tmax1, 2));
        if (c == 0) {
            rMax[wn * 64 + row0] = tmax0;
            rMax[wn * 64 + row1] = tmax1;
        }
        __syncthreads();
        float mn0 = fmaxf(m0, fmaxf(rMax[row0], rMax[64 + row0]));
        float mn1 = fmaxf(m1, fmaxf(rMax[row1], rMax[64 + row1]));
        float alpha0 = __expf(m0 - mn0), alpha1 = __expf(m1 - mn1);

        float ps0 = 0.f, ps1 = 0.f;
#pragma unroll
        for (int ni = 0; ni < 4; ni++) {
            int colb = 32 * wn + 8 * ni + 2 * c;
            float p0 = __expf(s[ni][0] - mn0);
            float p1 = __expf(s[ni][1] - mn0);
            float p2 = __expf(s[ni][2] - mn1);
            float p3 = __expf(s[ni][3] - mn1);
            ps0 += p0 + p1; ps1 += p2 + p3;
            sP[row0 * SP_STRIDE + colb]     = f2tf(p0);
            sP[row0 * SP_STRIDE + colb + 1] = f2tf(p1);
            sP[row1 * SP_STRIDE + colb]     = f2tf(p2);
            sP[row1 * SP_STRIDE + colb + 1] = f2tf(p3);
        }
        ps0 += __shfl_xor_sync(0xffffffffu, ps0, 1);
        ps0 += __shfl_xor_sync(0xffffffffu, ps0, 2);
        ps1 += __shfl_xor_sync(0xffffffffu, ps1, 1);
        ps1 += __shfl_xor_sync(0xffffffffu, ps1, 2);
        if (c == 0) {
            rSum[wn * 64 + row0] = ps0;
            rSum[wn * 64 + row1] = ps1;
        }

        // rescale O while rSum lands
        l0 = l0 * alpha0; l1 = l1 * alpha1;
#pragma unroll
        for (int nf = 0; nf < 16; nf++) {
            o[nf][0] *= alpha0; o[nf][1] *= alpha0;
            o[nf][2] *= alpha1; o[nf][3] *= alpha1;
        }
        m0 = mn0; m1 = mn1;

        // wait V(kt)
        if (kt + 1 < NT_) cp_wait<1>(); else cp_wait<0>();
        __syncthreads();
        l0 += rSum[row0] + rSum[64 + row0];
        l1 += rSum[row1] + rSum[64 + row1];

        // ---- PV ----
#pragma unroll
        for (int kf = 0; kf < 8; kf++) {
            float a0 = sP[row0 * SP_STRIDE + 8 * kf + c];
            float a1 = sP[row1 * SP_STRIDE + 8 * kf + c];
            float a2 = sP[row0 * SP_STRIDE + 8 * kf + c + 4];
            float a3 = sP[row1 * SP_STRIDE + 8 * kf + c + 4];
#pragma unroll
            for (int nf = 0; nf < 16; nf++) {
                int col = 128 * wn + 8 * nf + r;
                float b0 = sV[(8 * kf + c) * SV_STRIDE + col];
                float b1 = sV[(8 * kf + c + 4) * SV_STRIDE + col];
                mma8(o[nf][0], o[nf][1], o[nf][2], o[nf][3], a0, a1, a2, a3, b0, b1);
            }
        }
        __syncthreads();   // V + P buffers free for next iter
    }

    // ---- write out (tf32-rounded: feeds o-proj GEMM) ----
    const float inv0 = 1.0f / l0, inv1 = 1.0f / l1;
    const int b = bh >> 3, h = bh & 7;
    const size_t gr0 = ((size_t)b * S_ + qt * 64 + row0) * 2048 + h * 256;
    const size_t gr1 = ((size_t)b * S_ + qt * 64 + row1) * 2048 + h * 256;
#pragma unroll
    for (int nf = 0; nf < 16; nf++) {
        int col = 128 * wn + 8 * nf + 2 * c;
        O[gr0 + col]     = f2tf(o[nf][0] * inv0);
        O[gr0 + col + 1] = f2tf(o[nf][1] * inv0);
        O[gr1 + col]     = f2tf(o[nf][2] * inv1);
        O[gr1 + col + 1] = f2tf(o[nf][3] * inv1);
    }
}

// ---------------- launch ----------------
extern "C" void kernel_launch(void* const* d_in, const int* in_sizes, int n_in,
                              void* d_out, int out_size)
{
    const float* x         = (const float*)d_in[0];
    const int*   pos       = (const int*)  d_in[1];
    const float* w_dq_w    = (const float*)d_in[2];
    const float* w_dq_b    = (const float*)d_in[3];
    const float* q_norm_w  = (const float*)d_in[4];
    const float* w_uq_w    = (const float*)d_in[5];
    const float* w_uq_b    = (const float*)d_in[6];
    const float* w_dkv_w   = (const float*)d_in[7];
    const float* w_dkv_b   = (const float*)d_in[8];
    const float* kv_norm_w = (const float*)d_in[9];
    const float* w_ukv_w   = (const float*)d_in[10];
    const float* w_ukv_b   = (const float*)d_in[11];
    const float* w_o_w     = (const float*)d_in[12];
    const float* w_o_b     = (const float*)d_in[13];
    float* out = (float*)d_out;

    float *cq, *ckv, *q, *kv, *Qs, *Ks, *Vs, *attn, *wuq, *wukv, *wo;
    cudaGetSymbolAddress((void**)&cq,   g_cq);
    cudaGetSymbolAddress((void**)&ckv,  g_ckv);
    cudaGetSymbolAddress((void**)&q,    g_q);
    cudaGetSymbolAddress((void**)&kv,   g_kv);
    cudaGetSymbolAddress((void**)&Qs,   g_Qs);
    cudaGetSymbolAddress((void**)&Ks,   g_Ks);
    cudaGetSymbolAddress((void**)&Vs,   g_Vs);
    cudaGetSymbolAddress((void**)&attn, g_attn);
    cudaGetSymbolAddress((void**)&wuq,  g_wuq);
    cudaGetSymbolAddress((void**)&wukv, g_wukv);
    cudaGetSymbolAddress((void**)&wo,   g_wo);

    const int M = MROWS;

    // pre-round tf32 weights
    tfround_k<<<128 * 1024 / 1024, 256>>>(w_uq_w,  wuq,  128 * 1024);
    tfround_k<<<128 * 2560 / 1024, 256>>>(w_ukv_w, wukv, 128 * 2560);
    tfround_k<<<2048 * 1024 / 1024, 256>>>(w_o_w,  wo,   2048 * 1024);

    // down-projections (fp32)
    sgemm_bias<<<dim3(1, 32), 256>>>(x, w_dq_w,  w_dq_b,  cq,  M, 128, 1024, 1024);
    sgemm_bias<<<dim3(2, 32), 256>>>(x, w_dkv_w, w_dkv_b, ckv, M, 192, 1024, 1024);

    rmsnorm_kernel<<<M, 128>>>(cq,  q_norm_w,  128);
    rmsnorm_kernel<<<M, 128>>>(ckv, kv_norm_w, 192);
    rope_kernel<<<M, 32>>>(ckv, pos, 192, 128, 64);

    // up-projections (tf32, pipelined)
    gemm_tf32<<<dim3(8, 32), 256>>>(cq,  wuq,  w_uq_b,  q,  M, 1024, 128, 128);
    rope_kernel<<<M, 128>>>(q, pos, 1024, 768, 32);
    gemm_tf32<<<dim3(20, 32), 256>>>(ckv, wukv, w_ukv_b, kv, M, 2560, 128, 192);

    repack_kernel<<<B_ * NH_ * S_, 128>>>(q, kv, ckv, Qs, Ks, Vs);

    // attention (tf32, cp.async pipelined)
    const int smem = (64 * SQ_STRIDE * 3 + 64 * SV_STRIDE + 64 * SP_STRIDE + 256) * 4;
    cudaFuncSetAttribute(flash_tf32, cudaFuncAttributeMaxDynamicSharedMemorySize, smem);
    flash_tf32<<<dim3(S_ / 64, B_ * NH_), 256, smem>>>(Qs, Ks, Vs, attn);

    // output projection (tf32, pipelined)
    gemm_tf32<<<dim3(8, 32), 256>>>(attn, wo, w_o_b, out, M, 1024, 2048, 2048);
}

// round 6
// speedup vs baseline: 1.6704x; 1.6704x over previous
#include <cuda_runtime.h>
#include <cstdint>

#define B_   2
#define S_   2048
#define DIM_ 1024
#define NH_  8
#define MROWS (B_*S_)           // 4096
#define QD   128
#define VD   256

// ---------------- scratch ----------------
__device__ float g_cq  [MROWS*128];
__device__ float g_ckv [MROWS*192];
__device__ float g_q   [MROWS*1024];
__device__ float g_kv  [(size_t)MROWS*2560];
__device__ float g_Qs  [(size_t)B_*NH_*S_*QD];
__device__ float g_Ks  [(size_t)B_*NH_*S_*QD];
__device__ float g_Vs  [(size_t)B_*NH_*S_*VD];
__device__ float g_attn[(size_t)MROWS*2048];

// ---------------- tf32 helpers ----------------
__device__ __forceinline__ float f2tf(float x) {
    uint32_t u;
    asm("cvt.rna.tf32.f32 %0, %1;" : "=r"(u) : "f"(x));
    return __uint_as_float(u);
}

__device__ __forceinline__ void mma8(float& d0, float& d1, float& d2, float& d3,
                                     float a0, float a1, float a2, float a3,
                                     float b0, float b1)
{
    uint32_t A0 = __float_as_uint(a0), A1 = __float_as_uint(a1);
    uint32_t A2 = __float_as_uint(a2), A3 = __float_as_uint(a3);
    uint32_t B0 = __float_as_uint(b0), B1 = __float_as_uint(b1);
    asm volatile(
        "mma.sync.aligned.m16n8k8.row.col.f32.tf32.tf32.f32 "
        "{%0,%1,%2,%3},{%4,%5,%6,%7},{%8,%9},{%0,%1,%2,%3};\n"
        : "+f"(d0), "+f"(d1), "+f"(d2), "+f"(d3)
        : "r"(A0), "r"(A1), "r"(A2), "r"(A3), "r"(B0), "r"(B1));
}

// ---------------- fused fp32 down-projections: cq (N=128) + ckv (N=192) ----------------
// Tile: 128 rows x 64 cols, BK=8, 256 threads, each thread 8x4.
// blockIdx.x: 0-1 -> dq col tiles, 2-4 -> dkv col tiles. Grid (5, 32) = 160 CTAs.
__global__ void __launch_bounds__(256) down_proj_fused(
    const float* __restrict__ x,
    const float* __restrict__ w_dq,  const float* __restrict__ b_dq,
    const float* __restrict__ w_dkv, const float* __restrict__ b_dkv,
    float* __restrict__ cq, float* __restrict__ ckv)
{
    __shared__ float As[8][128];
    __shared__ float Bs[8][64];

    const int bx = blockIdx.x;
    const float* Bm; const float* bias; float* C; int N, bn;
    if (bx < 2) { Bm = w_dq;  bias = b_dq;  C = cq;  N = 128; bn = bx * 64; }
    else        { Bm = w_dkv; bias = b_dkv; C = ckv; N = 192; bn = (bx - 2) * 64; }

    const int tid = threadIdx.x;
    const int tx  = tid & 15;
    const int ty  = tid >> 4;
    const int bm  = blockIdx.y * 128;

    const int arow = tid >> 1, acol = (tid & 1) << 2;   // A: 128 rows x 8 cols
    const int brow = tid >> 4, bcol = (tid & 15) << 2;  // B (tid<128): 8 rows x 64 cols

    float acc[8][4];
#pragma unroll
    for (int i = 0; i < 8; i++)
#pragma unroll
        for (int j = 0; j < 4; j++) acc[i][j] = 0.f;

    for (int k0 = 0; k0 < 1024; k0 += 8) {
        float4 av = *(const float4*)&x[(size_t)(bm + arow) * 1024 + k0 + acol];
        float4 bv = make_float4(0.f, 0.f, 0.f, 0.f);
        if (tid < 128)
            bv = *(const float4*)&Bm[(size_t)(k0 + brow) * N + bn + bcol];

        __syncthreads();
        As[acol + 0][arow] = av.x;
        As[acol + 1][arow] = av.y;
        As[acol + 2][arow] = av.z;
        As[acol + 3][arow] = av.w;
        if (tid < 128)
            *(float4*)&Bs[brow][bcol] = bv;
        __syncthreads();

#pragma unroll
        for (int kk = 0; kk < 8; kk++) {
            float4 a0 = *(const float4*)&As[kk][ty * 4];
            float4 a1 = *(const float4*)&As[kk][64 + ty * 4];
            float4 b0 = *(const float4*)&Bs[kk][tx * 4];
            float a[8] = {a0.x, a0.y, a0.z, a0.w, a1.x, a1.y, a1.z, a1.w};
            float b[4] = {b0.x, b0.y, b0.z, b0.w};
#pragma unroll
            for (int i = 0; i < 8; i++)
#pragma unroll
                for (int j = 0; j < 4; j++)
                    acc[i][j] += a[i] * b[j];
        }
    }

#pragma unroll
    for (int i = 0; i < 8; i++) {
        int row = bm + ((i < 4) ? (ty * 4 + i) : (64 + ty * 4 + i - 4));
#pragma unroll
        for (int j = 0; j < 4; j++) {
            int col = bn + tx * 4 + j;
            C[(size_t)row * N + col] = acc[i][j] + bias[col];
        }
    }
}

// ---------------- tf32 tensor-core GEMM (round-4 proven version) ----------------
__global__ void __launch_bounds__(256) gemm_tf32(
    const float* __restrict__ A, const float* __restrict__ Bm,
    const float* __restrict__ bias, float* __restrict__ C,
    int M, int N, int K, int lda)
{
    __shared__ float As[128][20];
    __shared__ float Bs[16][136];

    const int tid  = threadIdx.x;
    const int wid  = tid >> 5;
    const int lane = tid & 31;
    const int bm   = blockIdx.y * 128;
    const int bn   = blockIdx.x * 128;
    const int wm   = (wid >> 2) * 64;
    const int wn   = (wid & 3) * 32;
    const int r    = lane >> 2;
    const int c    = lane & 3;

    float acc[4][4][4];
#pragma unroll
    for (int i = 0; i < 4; i++)
#pragma unroll
        for (int j = 0; j < 4; j++)
#pragma unroll
            for (int k = 0; k < 4; k++) acc[i][j][k] = 0.f;

    const int ar = tid >> 1, ac4 = (tid & 1) << 3;
    const int br = tid >> 4, bc4 = (tid & 15) << 3;

    for (int k0 = 0; k0 < K; k0 += 16) {
        float4 av0 = *(const float4*)&A[(size_t)(bm + ar) * lda + k0 + ac4];
        float4 av1 = *(const float4*)&A[(size_t)(bm + ar) * lda + k0 + ac4 + 4];
        float4 bv0 = make_float4(0.f, 0.f, 0.f, 0.f), bv1 = bv0;
        if (bn + bc4 < N)
            bv0 = *(const float4*)&Bm[(size_t)(k0 + br) * N + bn + bc4];
        if (bn + bc4 + 4 < N)
            bv1 = *(const float4*)&Bm[(size_t)(k0 + br) * N + bn + bc4 + 4];

        __syncthreads();
        As[ar][ac4 + 0] = f2tf(av0.x); As[ar][ac4 + 1] = f2tf(av0.y);
        As[ar][ac4 + 2] = f2tf(av0.z); As[ar][ac4 + 3] = f2tf(av0.w);
        As[ar][ac4 + 4] = f2tf(av1.x); As[ar][ac4 + 5] = f2tf(av1.y);
        As[ar][ac4 + 6] = f2tf(av1.z); As[ar][ac4 + 7] = f2tf(av1.w);
        Bs[br][bc4 + 0] = f2tf(bv0.x); Bs[br][bc4 + 1] = f2tf(bv0.y);
        Bs[br][bc4 + 2] = f2tf(bv0.z); Bs[br][bc4 + 3] = f2tf(bv0.w);
        Bs[br][bc4 + 4] = f2tf(bv1.x); Bs[br][bc4 + 5] = f2tf(bv1.y);
        Bs[br][bc4 + 6] = f2tf(bv1.z); Bs[br][bc4 + 7] = f2tf(bv1.w);
        __syncthreads();

#pragma unroll
        for (int kk = 0; kk < 16; kk += 8) {
            float a[4][4], b[4][2];
#pragma unroll
            for (int mi = 0; mi < 4; mi++) {
                int row = wm + 16 * mi;
                a[mi][0] = As[row + r][kk + c];
                a[mi][1] = As[row + r + 8][kk + c];
                a[mi][2] = As[row + r][kk + c + 4];
                a[mi][3] = As[row + r + 8][kk + c + 4];
            }
#pragma unroll
            for (int ni = 0; ni < 4; ni++) {
                int col = wn + 8 * ni + r;
                b[ni][0] = Bs[kk + c][col];
                b[ni][1] = Bs[kk + c + 4][col];
            }
#pragma unroll
            for (int mi = 0; mi < 4; mi++)
#pragma unroll
                for (int ni = 0; ni < 4; ni++)
                    mma8(acc[mi][ni][0], acc[mi][ni][1], acc[mi][ni][2], acc[mi][ni][3],
                         a[mi][0], a[mi][1], a[mi][2], a[mi][3], b[ni][0], b[ni][1]);
        }
    }

#pragma unroll
    for (int mi = 0; mi < 4; mi++) {
        int row0 = bm + wm + 16 * mi + r;
#pragma unroll
        for (int ni = 0; ni < 4; ni++) {
            int col0 = bn + wn + 8 * ni + 2 * c;
            if (col0 < N) {
                C[(size_t)row0 * N + col0]       = acc[mi][ni][0] + bias[col0];
                C[(size_t)(row0 + 8) * N + col0] = acc[mi][ni][2] + bias[col0];
            }
            if (col0 + 1 < N) {
                C[(size_t)row0 * N + col0 + 1]       = acc[mi][ni][1] + bias[col0 + 1];
                C[(size_t)(row0 + 8) * N + col0 + 1] = acc[mi][ni][3] + bias[col0 + 1];
            }
        }
    }
}

// ---------------- small kernels ----------------
__global__ void rmsnorm_kernel(float* __restrict__ buf, const float* __restrict__ w,
                               int stride)
{
    const int row = blockIdx.x;
    const int tid = threadIdx.x;
    float v = buf[(size_t)row * stride + tid];
    float s = v * v;
#pragma unroll
    for (int o = 16; o; o >>= 1) s += __shfl_xor_sync(0xffffffffu, s, o);
    __shared__ float ws[4];
    if ((tid & 31) == 0) ws[tid >> 5] = s;
    __syncthreads();
    float tot = ws[0] + ws[1] + ws[2] + ws[3];
    float rr = rsqrtf(tot / (float)blockDim.x + 1e-8f);
    buf[(size_t)row * stride + tid] = w[tid] * v * rr;
}

__global__ void rope_kernel(float* __restrict__ buf, const int* __restrict__ pos,
                            int stride, int col_off, int hd)
{
    const int row = blockIdx.x;
    const int tid = threadIdx.x;
    const int half = hd >> 1;
    const int h = tid / half, i = tid % half;
    float p = (float)pos[row];
    float freq = powf(10000.0f, -2.0f * (float)i / (float)hd);
    float ang = p * freq;
    float sn, cs;
    sincosf(ang, &sn, &cs);
    size_t base = (size_t)row * stride + col_off + h * hd + 2 * i;
    float xe = buf[base], xo = buf[base + 1];
    buf[base]     = xe * cs - xo * sn;
    buf[base + 1] = xe * sn + xo * cs;
}

__global__ void repack_kernel(const float* __restrict__ q, const float* __restrict__ kv,
                              const float* __restrict__ ckv,
                              float* __restrict__ Qo, float* __restrict__ Ko,
                              float* __restrict__ Vo)
{
    const int bhs = blockIdx.x;
    const int d   = threadIdx.x;
    const int s   = bhs & (S_ - 1);
    const int bh  = bhs >> 11;
    const int h   = bh & 7;
    const int b   = bh >> 3;
    const size_t row = (size_t)b * S_ + s;
    const size_t o128 = (size_t)bhs * 128, o256 = (size_t)bhs * 256;

    Qo[o128 + d] = (d < 96) ? q[row * 1024 + h * 96 + d]
                            : q[row * 1024 + 768 + h * 32 + (d - 96)];
    Ko[o128 + d] = (d < 64) ? kv[row * 2560 + h * 64 + d]
                            : ckv[row * 192 + 128 + (d - 64)];
    Vo[o256 + d]       = kv[row * 2560 + 512 + (size_t)h * 256 + d];
    Vo[o256 + 128 + d] = kv[row * 2560 + 512 + (size_t)h * 256 + 128 + d];
}

// ---------------- tf32 flash attention (round-4 proven version) ----------------
#define SQ_STRIDE 132
#define SV_STRIDE 264
#define SP_STRIDE 68

__global__ void __launch_bounds__(256) flash_tf32(
    const float* __restrict__ Q, const float* __restrict__ K,
    const float* __restrict__ V, float* __restrict__ O)
{
    extern __shared__ float sm[];
    float* sQ  = sm;
    float* sK  = sQ + 64 * SQ_STRIDE;
    float* sV  = sK + 64 * SQ_STRIDE;
    float* sP  = sV + 64 * SV_STRIDE;
    float* rMax = sP + 64 * SP_STRIDE;
    float* rSum = rMax + 128;

    const int tid  = threadIdx.x;
    const int wid  = tid >> 5;
    const int lane = tid & 31;
    const int wm   = wid >> 1;
    const int wn   = wid & 1;
    const int r    = lane >> 2;
    const int c    = lane & 3;
    const int bh   = blockIdx.y;
    const int qt   = blockIdx.x;
    const float scale = 0.08838834764831845f;

    const float* Qg = Q + ((size_t)bh * S_ + qt * 64) * QD;
    for (int i = tid; i < 64 * 32; i += 256) {
        int row = i >> 5, col = (i & 31) << 2;
        float4 v = *(const float4*)&Qg[row * QD + col];
        float* d = &sQ[row * SQ_STRIDE + col];
        d[0] = f2tf(v.x * scale); d[1] = f2tf(v.y * scale);
        d[2] = f2tf(v.z * scale); d[3] = f2tf(v.w * scale);
    }

    float o[16][4];
#pragma unroll
    for (int i = 0; i < 16; i++)
#pragma unroll
        for (int j = 0; j < 4; j++) o[i][j] = 0.f;
    float m0 = -1e30f, m1 = -1e30f, l0 = 0.f, l1 = 0.f;

    const int row0 = 16 * wm + r;
    const int row1 = row0 + 8;

    for (int kt = 0; kt < S_ / 64; kt++) {
        __syncthreads();
        const float* Kg = K + ((size_t)bh * S_ + kt * 64) * QD;
        for (int i = tid; i < 64 * 32; i += 256) {
            int row = i >> 5, col = (i & 31) << 2;
            float4 v = *(const float4*)&Kg[row * QD + col];
            float* d = &sK[row * SQ_STRIDE + col];
            d[0] = f2tf(v.x); d[1] = f2tf(v.y); d[2] = f2tf(v.z); d[3] = f2tf(v.w);
        }
        const float* Vg = V + ((size_t)bh * S_ + kt * 64) * VD;
        for (int i = tid; i < 64 * 64; i += 256) {
            int row = i >> 6, col = (i & 63) << 2;
            float4 v = *(const float4*)&Vg[row * VD + col];
            float* d = &sV[row * SV_STRIDE + col];
            d[0] = f2tf(v.x); d[1] = f2tf(v.y); d[2] = f2tf(v.z); d[3] = f2tf(v.w);
        }
        __syncthreads();

        float s[4][4];
#pragma unroll
        for (int ni = 0; ni < 4; ni++)
#pragma unroll
            for (int j = 0; j < 4; j++) s[ni][j] = 0.f;

#pragma unroll
        for (int kk = 0; kk < 128; kk += 8) {
            float a0 = sQ[(16 * wm + r) * SQ_STRIDE + kk + c];
            float a1 = sQ[(16 * wm + r + 8) * SQ_STRIDE + kk + c];
            float a2 = sQ[(16 * wm + r) * SQ_STRIDE + kk + c + 4];
            float a3 = sQ[(16 * wm + r + 8) * SQ_STRIDE + kk + c + 4];
#pragma unroll
            for (int ni = 0; ni < 4; ni++) {
                int key = 32 * wn + 8 * ni + r;
                float b0 = sK[key * SQ_STRIDE + kk + c];
                float b1 = sK[key * SQ_STRIDE + kk + c + 4];
                mma8(s[ni][0], s[ni][1], s[ni][2], s[ni][3], a0, a1, a2, a3, b0, b1);
            }
        }

        float tmax0 = -1e30f, tmax1 = -1e30f;
#pragma unroll
        for (int ni = 0; ni < 4; ni++) {
            tmax0 = fmaxf(tmax0, fmaxf(s[ni][0], s[ni][1]));
            tmax1 = fmaxf(tmax1, fmaxf(s[ni][2], s[ni][3]));
        }
        tmax0 = fmaxf(tmax0, __shfl_xor_sync(0xffffffffu, tmax0, 1));
        tmax0 = fmaxf(tmax0, __shfl_xor_sync(0xffffffffu, tmax0, 2));
        tmax1 = fmaxf(tmax1, __shfl_xor_sync(0xffffffffu, tmax1, 1));
        tmax1 = fmaxf(tmax1, __shfl_xor_sync(0xffffffffu, tmax1, 2));
        if (c == 0) {
            rMax[wn * 64 + row0] = tmax0;
            rMax[wn * 64 + row1] = tmax1;
        }
        __syncthreads();
        float tile0 = fmaxf(rMax[row0], rMax[64 + row0]);
        float tile1 = fmaxf(rMax[row1], rMax[64 + row1]);
        float mn0 = fmaxf(m0, tile0), mn1 = fmaxf(m1, tile1);
        float alpha0 = __expf(m0 - mn0), alpha1 = __expf(m1 - mn1);

        float ps0 = 0.f, ps1 = 0.f;
#pragma unroll
        for (int ni = 0; ni < 4; ni++) {
            int colb = 32 * wn + 8 * ni + 2 * c;
            float p0 = __expf(s[ni][0] - mn0);
            float p1 = __expf(s[ni][1] - mn0);
            float p2 = __expf(s[ni][2] - mn1);
            float p3 = __expf(s[ni][3] - mn1);
            ps0 += p0 + p1; ps1 += p2 + p3;
            sP[row0 * SP_STRIDE + colb]     = f2tf(p0);
            sP[row0 * SP_STRIDE + colb + 1] = f2tf(p1);
            sP[row1 * SP_STRIDE + colb]     = f2tf(p2);
            sP[row1 * SP_STRIDE + colb + 1] = f2tf(p3);
        }
        ps0 += __shfl_xor_sync(0xffffffffu, ps0, 1);
        ps0 += __shfl_xor_sync(0xffffffffu, ps0, 2);
        ps1 += __shfl_xor_sync(0xffffffffu, ps1, 1);
        ps1 += __shfl_xor_sync(0xffffffffu, ps1, 2);
        if (c == 0) {
            rSum[wn * 64 + row0] = ps0;
            rSum[wn * 64 + row1] = ps1;
        }
        __syncthreads();
        l0 = l0 * alpha0 + rSum[row0] + rSum[64 + row0];
        l1 = l1 * alpha1 + rSum[row1] + rSum[64 + row1];
        m0 = mn0; m1 = mn1;

#pragma unroll
        for (int nf = 0; nf < 16; nf++) {
            o[nf][0] *= alpha0; o[nf][1] *= alpha0;
            o[nf][2] *= alpha1; o[nf][3] *= alpha1;
        }

#pragma unroll
        for (int kf = 0; kf < 8; kf++) {
            float a0 = sP[(16 * wm + r) * SP_STRIDE + 8 * kf + c];
            float a1 = sP[(16 * wm + r + 8) * SP_STRIDE + 8 * kf + c];
            float a2 = sP[(16 * wm + r) * SP_STRIDE + 8 * kf + c + 4];
            float a3 = sP[(16 * wm + r + 8) * SP_STRIDE + 8 * kf + c + 4];
#pragma unroll
            for (int nf = 0; nf < 16; nf++) {
                int col = 128 * wn + 8 * nf + r;
                float b0 = sV[(8 * kf + c) * SV_STRIDE + col];
                float b1 = sV[(8 * kf + c + 4) * SV_STRIDE + col];
                mma8(o[nf][0], o[nf][1], o[nf][2], o[nf][3], a0, a1, a2, a3, b0, b1);
            }
        }
    }

    const float inv0 = 1.0f / l0, inv1 = 1.0f / l1;
    const int b = bh >> 3, h = bh & 7;
    const size_t gr0 = ((size_t)b * S_ + qt * 64 + row0) * 2048 + h * 256;
    const size_t gr1 = ((size_t)b * S_ + qt * 64 + row1) * 2048 + h * 256;
#pragma unroll
    for (int nf = 0; nf < 16; nf++) {
        int col = 128 * wn + 8 * nf + 2 * c;
        O[gr0 + col]     = o[nf][0] * inv0;
        O[gr0 + col + 1] = o[nf][1] * inv0;
        O[gr1 + col]     = o[nf][2] * inv1;
        O[gr1 + col + 1] = o[nf][3] * inv1;
    }
}

// ---------------- launch ----------------
extern "C" void kernel_launch(void* const* d_in, const int* in_sizes, int n_in,
                              void* d_out, int out_size)
{
    const float* x         = (const float*)d_in[0];
    const int*   pos       = (const int*)  d_in[1];
    const float* w_dq_w    = (const float*)d_in[2];
    const float* w_dq_b    = (const float*)d_in[3];
    const float* q_norm_w  = (const float*)d_in[4];
    const float* w_uq_w    = (const float*)d_in[5];
    const float* w_uq_b    = (const float*)d_in[6];
    const float* w_dkv_w   = (const float*)d_in[7];
    const float* w_dkv_b   = (const float*)d_in[8];
    const float* kv_norm_w = (const float*)d_in[9];
    const float* w_ukv_w   = (const float*)d_in[10];
    const float* w_ukv_b   = (const float*)d_in[11];
    const float* w_o_w     = (const float*)d_in[12];
    const float* w_o_b     = (const float*)d_in[13];
    float* out = (float*)d_out;

    float *cq, *ckv, *q, *kv, *Qs, *Ks, *Vs, *attn;
    cudaGetSymbolAddress((void**)&cq,   g_cq);
    cudaGetSymbolAddress((void**)&ckv,  g_ckv);
    cudaGetSymbolAddress((void**)&q,    g_q);
    cudaGetSymbolAddress((void**)&kv,   g_kv);
    cudaGetSymbolAddress((void**)&Qs,   g_Qs);
    cudaGetSymbolAddress((void**)&Ks,   g_Ks);
    cudaGetSymbolAddress((void**)&Vs,   g_Vs);
    cudaGetSymbolAddress((void**)&attn, g_attn);

    const int M = MROWS;

    // fused fp32 down-projections: one launch, grid (5, 32) = 160 CTAs
    down_proj_fused<<<dim3(5, 32), 256>>>(x, w_dq_w, w_dq_b, w_dkv_w, w_dkv_b, cq, ckv);

    rmsnorm_kernel<<<M, 128>>>(cq,  q_norm_w,  128);
    rmsnorm_kernel<<<M, 128>>>(ckv, kv_norm_w, 192);
    rope_kernel<<<M, 32>>>(ckv, pos, 192, 128, 64);

    // up-projections (tf32 tensor cores)
    gemm_tf32<<<dim3(8, 32), 256>>>(cq,  w_uq_w,  w_uq_b,  q,  M, 1024, 128, 128);
    rope_kernel<<<M, 128>>>(q, pos, 1024, 768, 32);
    gemm_tf32<<<dim3(20, 32), 256>>>(ckv, w_ukv_w, w_ukv_b, kv, M, 2560, 128, 192);

    repack_kernel<<<B_ * NH_ * S_, 128>>>(q, kv, ckv, Qs, Ks, Vs);

    // attention (tf32 tensor cores)
    const int smem = (64 * SQ_STRIDE * 2 + 64 * SV_STRIDE + 64 * SP_STRIDE + 256) * 4;
    cudaFuncSetAttribute(flash_tf32, cudaFuncAttributeMaxDynamicSharedMemorySize, smem);
    flash_tf32<<<dim3(S_ / 64, B_ * NH_), 256, smem>>>(Qs, Ks, Vs, attn);

    // output projection (tf32)
    gemm_tf32<<<dim3(8, 32), 256>>>(attn, w_o_w, w_o_b, out, M, 1024, 2048, 2048);
}

// round 14
// speedup vs baseline: 2.5687x; 1.5378x over previous
#include <cuda_runtime.h>
#include <cuda_fp16.h>
#include <cstdint>

#define B_   2
#define S_   2048
#define DIM_ 1024
#define NH_  8
#define MROWS (B_*S_)           // 4096
#define QD   128
#define VD   256

// ---------------- scratch ----------------
__device__ float g_cq  [MROWS*128];
__device__ float g_ckv [MROWS*192];
__device__ float g_q   [MROWS*1024];
__device__ float g_kv  [(size_t)MROWS*2560];
__device__ float g_Qs  [(size_t)B_*NH_*S_*QD];
__device__ float g_Ks  [(size_t)B_*NH_*S_*QD];
__device__ float g_Vs  [(size_t)B_*NH_*S_*VD];
__device__ float g_attn[(size_t)MROWS*2048];

// ---------------- helpers ----------------
__device__ __forceinline__ float f2tf(float x) {
    uint32_t u;
    asm("cvt.rna.tf32.f32 %0, %1;" : "=r"(u) : "f"(x));
    return __uint_as_float(u);
}

__device__ __forceinline__ void mma8(float& d0, float& d1, float& d2, float& d3,
                                     float a0, float a1, float a2, float a3,
                                     float b0, float b1)
{
    uint32_t A0 = __float_as_uint(a0), A1 = __float_as_uint(a1);
    uint32_t A2 = __float_as_uint(a2), A3 = __float_as_uint(a3);
    uint32_t B0 = __float_as_uint(b0), B1 = __float_as_uint(b1);
    asm volatile(
        "mma.sync.aligned.m16n8k8.row.col.f32.tf32.tf32.f32 "
        "{%0,%1,%2,%3},{%4,%5,%6,%7},{%8,%9},{%0,%1,%2,%3};\n"
        : "+f"(d0), "+f"(d1), "+f"(d2), "+f"(d3)
        : "r"(A0), "r"(A1), "r"(A2), "r"(A3), "r"(B0), "r"(B1));
}

__device__ __forceinline__ void mma_f16(float* d,
                                        uint32_t a0, uint32_t a1, uint32_t a2, uint32_t a3,
                                        uint32_t b0, uint32_t b1)
{
    asm volatile(
        "mma.sync.aligned.m16n8k16.row.col.f32.f16.f16.f32 "
        "{%0,%1,%2,%3},{%4,%5,%6,%7},{%8,%9},{%0,%1,%2,%3};\n"
        : "+f"(d[0]), "+f"(d[1]), "+f"(d[2]), "+f"(d[3])
        : "r"(a0), "r"(a1), "r"(a2), "r"(a3), "r"(b0), "r"(b1));
}

// ---------------- fused fp32 down-projections: cq (N=128) + ckv (N=192) ----------------
__global__ void __launch_bounds__(256) down_proj_fused(
    const float* __restrict__ x,
    const float* __restrict__ w_dq,  const float* __restrict__ b_dq,
    const float* __restrict__ w_dkv, const float* __restrict__ b_dkv,
    float* __restrict__ cq, float* __restrict__ ckv)
{
    __shared__ float As[8][128];
    __shared__ float Bs[8][64];

    const int bx = blockIdx.x;
    const float* Bm; const float* bias; float* C; int N, bn;
    if (bx < 2) { Bm = w_dq;  bias = b_dq;  C = cq;  N = 128; bn = bx * 64; }
    else        { Bm = w_dkv; bias = b_dkv; C = ckv; N = 192; bn = (bx - 2) * 64; }

    const int tid = threadIdx.x;
    const int tx  = tid & 15;
    const int ty  = tid >> 4;
    const int bm  = blockIdx.y * 128;

    const int arow = tid >> 1, acol = (tid & 1) << 2;
    const int brow = tid >> 4, bcol = (tid & 15) << 2;

    float acc[8][4];
#pragma unroll
    for (int i = 0; i < 8; i++)
#pragma unroll
        for (int j = 0; j < 4; j++) acc[i][j] = 0.f;

    for (int k0 = 0; k0 < 1024; k0 += 8) {
        float4 av = *(const float4*)&x[(size_t)(bm + arow) * 1024 + k0 + acol];
        float4 bv = make_float4(0.f, 0.f, 0.f, 0.f);
        if (tid < 128)
            bv = *(const float4*)&Bm[(size_t)(k0 + brow) * N + bn + bcol];

        __syncthreads();
        As[acol + 0][arow] = av.x;
        As[acol + 1][arow] = av.y;
        As[acol + 2][arow] = av.z;
        As[acol + 3][arow] = av.w;
        if (tid < 128)
            *(float4*)&Bs[brow][bcol] = bv;
        __syncthreads();

#pragma unroll
        for (int kk = 0; kk < 8; kk++) {
            float4 a0 = *(const float4*)&As[kk][ty * 4];
            float4 a1 = *(const float4*)&As[kk][64 + ty * 4];
            float4 b0 = *(const float4*)&Bs[kk][tx * 4];
            float a[8] = {a0.x, a0.y, a0.z, a0.w, a1.x, a1.y, a1.z, a1.w};
            float b[4] = {b0.x, b0.y, b0.z, b0.w};
#pragma unroll
            for (int i = 0; i < 8; i++)
#pragma unroll
                for (int j = 0; j < 4; j++)
                    acc[i][j] += a[i] * b[j];
        }
    }

#pragma unroll
    for (int i = 0; i < 8; i++) {
        int row = bm + ((i < 4) ? (ty * 4 + i) : (64 + ty * 4 + i - 4));
#pragma unroll
        for (int j = 0; j < 4; j++) {
            int col = bn + tx * 4 + j;
            C[(size_t)row * N + col] = acc[i][j] + bias[col];
        }
    }
}

// ---------------- tf32 tensor-core GEMM (proven) ----------------
__global__ void __launch_bounds__(256) gemm_tf32(
    const float* __restrict__ A, const float* __restrict__ Bm,
    const float* __restrict__ bias, float* __restrict__ C,
    int M, int N, int K, int lda)
{
    __shared__ float As[128][20];
    __shared__ float Bs[16][136];

    const int tid  = threadIdx.x;
    const int wid  = tid >> 5;
    const int lane = tid & 31;
    const int bm   = blockIdx.y * 128;
    const int bn   = blockIdx.x * 128;
    const int wm   = (wid >> 2) * 64;
    const int wn   = (wid & 3) * 32;
    const int r    = lane >> 2;
    const int c    = lane & 3;

    float acc[4][4][4];
#pragma unroll
    for (int i = 0; i < 4; i++)
#pragma unroll
        for (int j = 0; j < 4; j++)
#pragma unroll
            for (int k = 0; k < 4; k++) acc[i][j][k] = 0.f;

    const int ar = tid >> 1, ac4 = (tid & 1) << 3;
    const int br = tid >> 4, bc4 = (tid & 15) << 3;

    for (int k0 = 0; k0 < K; k0 += 16) {
        float4 av0 = *(const float4*)&A[(size_t)(bm + ar) * lda + k0 + ac4];
        float4 av1 = *(const float4*)&A[(size_t)(bm + ar) * lda + k0 + ac4 + 4];
        float4 bv0 = make_float4(0.f, 0.f, 0.f, 0.f), bv1 = bv0;
        if (bn + bc4 < N)
            bv0 = *(const float4*)&Bm[(size_t)(k0 + br) * N + bn + bc4];
        if (bn + bc4 + 4 < N)
            bv1 = *(const float4*)&Bm[(size_t)(k0 + br) * N + bn + bc4 + 4];

        __syncthreads();
        As[ar][ac4 + 0] = f2tf(av0.x); As[ar][ac4 + 1] = f2tf(av0.y);
        As[ar][ac4 + 2] = f2tf(av0.z); As[ar][ac4 + 3] = f2tf(av0.w);
        As[ar][ac4 + 4] = f2tf(av1.x); As[ar][ac4 + 5] = f2tf(av1.y);
        As[ar][ac4 + 6] = f2tf(av1.z); As[ar][ac4 + 7] = f2tf(av1.w);
        Bs[br][bc4 + 0] = f2tf(bv0.x); Bs[br][bc4 + 1] = f2tf(bv0.y);
        Bs[br][bc4 + 2] = f2tf(bv0.z); Bs[br][bc4 + 3] = f2tf(bv0.w);
        Bs[br][bc4 + 4] = f2tf(bv1.x); Bs[br][bc4 + 5] = f2tf(bv1.y);
        Bs[br][bc4 + 6] = f2tf(bv1.z); Bs[br][bc4 + 7] = f2tf(bv1.w);
        __syncthreads();

#pragma unroll
        for (int kk = 0; kk < 16; kk += 8) {
            float a[4][4], b[4][2];
#pragma unroll
            for (int mi = 0; mi < 4; mi++) {
                int row = wm + 16 * mi;
                a[mi][0] = As[row + r][kk + c];
                a[mi][1] = As[row + r + 8][kk + c];
                a[mi][2] = As[row + r][kk + c + 4];
                a[mi][3] = As[row + r + 8][kk + c + 4];
            }
#pragma unroll
            for (int ni = 0; ni < 4; ni++) {
                int col = wn + 8 * ni + r;
                b[ni][0] = Bs[kk + c][col];
                b[ni][1] = Bs[kk + c + 4][col];
            }
#pragma unroll
            for (int mi = 0; mi < 4; mi++)
#pragma unroll
                for (int ni = 0; ni < 4; ni++)
                    mma8(acc[mi][ni][0], acc[mi][ni][1], acc[mi][ni][2], acc[mi][ni][3],
                         a[mi][0], a[mi][1], a[mi][2], a[mi][3], b[ni][0], b[ni][1]);
        }
    }

#pragma unroll
    for (int mi = 0; mi < 4; mi++) {
        int row0 = bm + wm + 16 * mi + r;
#pragma unroll
        for (int ni = 0; ni < 4; ni++) {
            int col0 = bn + wn + 8 * ni + 2 * c;
            if (col0 < N) {
                C[(size_t)row0 * N + col0]       = acc[mi][ni][0] + bias[col0];
                C[(size_t)(row0 + 8) * N + col0] = acc[mi][ni][2] + bias[col0];
            }
            if (col0 + 1 < N) {
                C[(size_t)row0 * N + col0 + 1]       = acc[mi][ni][1] + bias[col0 + 1];
                C[(size_t)(row0 + 8) * N + col0 + 1] = acc[mi][ni][3] + bias[col0 + 1];
            }
        }
    }
}

// ---------------- small kernels ----------------
__global__ void rmsnorm_kernel(float* __restrict__ buf, const float* __restrict__ w,
                               int stride)
{
    const int row = blockIdx.x;
    const int tid = threadIdx.x;
    float v = buf[(size_t)row * stride + tid];
    float s = v * v;
#pragma unroll
    for (int o = 16; o; o >>= 1) s += __shfl_xor_sync(0xffffffffu, s, o);
    __shared__ float ws[4];
    if ((tid & 31) == 0) ws[tid >> 5] = s;
    __syncthreads();
    float tot = ws[0] + ws[1] + ws[2] + ws[3];
    float rr = rsqrtf(tot / (float)blockDim.x + 1e-8f);
    buf[(size_t)row * stride + tid] = w[tid] * v * rr;
}

__global__ void rope_kernel(float* __restrict__ buf, const int* __restrict__ pos,
                            int stride, int col_off, int hd)
{
    const int row = blockIdx.x;
    const int tid = threadIdx.x;
    const int half = hd >> 1;
    const int h = tid / half, i = tid % half;
    float p = (float)pos[row];
    float freq = powf(10000.0f, -2.0f * (float)i / (float)hd);
    float ang = p * freq;
    float sn, cs;
    sincosf(ang, &sn, &cs);
    size_t base = (size_t)row * stride + col_off + h * hd + 2 * i;
    float xe = buf[base], xo = buf[base + 1];
    buf[base]     = xe * cs - xo * sn;
    buf[base + 1] = xe * sn + xo * cs;
}

__global__ void repack_kernel(const float* __restrict__ q, const float* __restrict__ kv,
                              const float* __restrict__ ckv,
                              float* __restrict__ Qo, float* __restrict__ Ko,
                              float* __restrict__ Vo)
{
    const int bhs = blockIdx.x;
    const int d   = threadIdx.x;
    const int s   = bhs & (S_ - 1);
    const int bh  = bhs >> 11;
    const int h   = bh & 7;
    const int b   = bh >> 3;
    const size_t row = (size_t)b * S_ + s;
    const size_t o128 = (size_t)bhs * 128, o256 = (size_t)bhs * 256;

    Qo[o128 + d] = (d < 96) ? q[row * 1024 + h * 96 + d]
                            : q[row * 1024 + 768 + h * 32 + (d - 96)];
    Ko[o128 + d] = (d < 64) ? kv[row * 2560 + h * 64 + d]
                            : ckv[row * 192 + 128 + (d - 64)];
    Vo[o256 + d]       = kv[row * 2560 + 512 + (size_t)h * 256 + d];
    Vo[o256 + 128 + d] = kv[row * 2560 + 512 + (size_t)h * 256 + 128 + d];
}

// ---------------- flash attention: tf32 QK^T, fp16 PV ----------------
// smem: sQ 64x132 f32 | sK 64x132 f32 | sVT 256x72 f16 (V^T) | sPT 64x72 f16 | rMax/rSum
// total 114688 B; __launch_bounds__(256,2) -> 2 CTAs/SM.
#define SQ_STRIDE 132
#define VT_STRIDE 72
#define PT_STRIDE 72
#define FLASH_SMEM 114688

__global__ void __launch_bounds__(256, 2) flash_tf32(
    const float* __restrict__ Q, const float* __restrict__ K,
    const float* __restrict__ V, float* __restrict__ O)
{
    extern __shared__ float sm[];
    float* sQ = sm;                                   // 64*132 f32
    float* sK = sQ + 64 * SQ_STRIDE;                  // 64*132 f32
    __half* sVT = (__half*)(sK + 64 * SQ_STRIDE);     // 256*72 f16
    __half* sPT = sVT + 256 * VT_STRIDE;              // 64*72 f16
    float* rMax = (float*)(sPT + 64 * PT_STRIDE);     // 2*64
    float* rSum = rMax + 128;                         // 2*64

    const int tid  = threadIdx.x;
    const int wid  = tid >> 5;
    const int lane = tid & 31;
    const int wm   = wid >> 1;
    const int wn   = wid & 1;
    const int r    = lane >> 2;
    const int c    = lane & 3;
    const int bh   = blockIdx.y;
    const int qt   = blockIdx.x;
    const float scale = 0.08838834764831845f;   // 1/sqrt(128)

    // Q tile (scaled, tf32-rounded)
    const float* Qg = Q + ((size_t)bh * S_ + qt * 64) * QD;
    for (int i = tid; i < 64 * 32; i += 256) {
        int row = i >> 5, col = (i & 31) << 2;
        float4 v = *(const float4*)&Qg[row * QD + col];
        float* d = &sQ[row * SQ_STRIDE + col];
        d[0] = f2tf(v.x * scale); d[1] = f2tf(v.y * scale);
        d[2] = f2tf(v.z * scale); d[3] = f2tf(v.w * scale);
    }

    float o[16][4];
#pragma unroll
    for (int i = 0; i < 16; i++)
#pragma unroll
        for (int j = 0; j < 4; j++) o[i][j] = 0.f;
    float m0 = -1e30f, m1 = -1e30f, l0 = 0.f, l1 = 0.f;

    const int row0 = 16 * wm + r;
    const int row1 = row0 + 8;

    for (int kt = 0; kt < S_ / 64; kt++) {
        __syncthreads();
        // K tile -> tf32 smem
        const float* Kg = K + ((size_t)bh * S_ + kt * 64) * QD;
        for (int i = tid; i < 64 * 32; i += 256) {
            int row = i >> 5, col = (i & 31) << 2;
            float4 v = *(const float4*)&Kg[row * QD + col];
            float* d = &sK[row * SQ_STRIDE + col];
            d[0] = f2tf(v.x); d[1] = f2tf(v.y); d[2] = f2tf(v.z); d[3] = f2tf(v.w);
        }
        // V tile -> transposed fp16 smem: sVT[col][k]; thread owns col = tid
        {
            const float* vg = V + ((size_t)bh * S_ + (size_t)kt * 64) * VD + tid;
            __half* vd = sVT + tid * VT_STRIDE;
#pragma unroll
            for (int g = 0; g < 16; g++) {
                float v0 = vg[(4 * g + 0) * VD];
                float v1 = vg[(4 * g + 1) * VD];
                float v2 = vg[(4 * g + 2) * VD];
                float v3 = vg[(4 * g + 3) * VD];
                __half2 lo = __floats2half2_rn(v0, v1);
                __half2 hi = __floats2half2_rn(v2, v3);
                uint2 pk;
                pk.x = *(uint32_t*)&lo;
                pk.y = *(uint32_t*)&hi;
                *(uint2*)&vd[4 * g] = pk;
            }
        }
        __syncthreads();

        // ---- S = Q @ K^T (tf32, warp: 16 rows x 32 keys) ----
        float s[4][4];
#pragma unroll
        for (int ni = 0; ni < 4; ni++)
#pragma unroll
            for (int j = 0; j < 4; j++) s[ni][j] = 0.f;

#pragma unroll
        for (int kk = 0; kk < 128; kk += 8) {
            float a0 = sQ[row0 * SQ_STRIDE + kk + c];
            float a1 = sQ[row1 * SQ_STRIDE + kk + c];
            float a2 = sQ[row0 * SQ_STRIDE + kk + c + 4];
            float a3 = sQ[row1 * SQ_STRIDE + kk + c + 4];
#pragma unroll
            for (int ni = 0; ni < 4; ni++) {
                int key = 32 * wn + 8 * ni + r;
                float b0 = sK[key * SQ_STRIDE + kk + c];
                float b1 = sK[key * SQ_STRIDE + kk + c + 4];
                mma8(s[ni][0], s[ni][1], s[ni][2], s[ni][3], a0, a1, a2, a3, b0, b1);
            }
        }

        // ---- online softmax ----
        float tmax0 = -1e30f, tmax1 = -1e30f;
#pragma unroll
        for (int ni = 0; ni < 4; ni++) {
            tmax0 = fmaxf(tmax0, fmaxf(s[ni][0], s[ni][1]));
            tmax1 = fmaxf(tmax1, fmaxf(s[ni][2], s[ni][3]));
        }
        tmax0 = fmaxf(tmax0, __shfl_xor_sync(0xffffffffu, tmax0, 1));
        tmax0 = fmaxf(tmax0, __shfl_xor_sync(0xffffffffu, tmax0, 2));
        tmax1 = fmaxf(tmax1, __shfl_xor_sync(0xffffffffu, tmax1, 1));
        tmax1 = fmaxf(tmax1, __shfl_xor_sync(0xffffffffu, tmax1, 2));
        if (c == 0) {
            rMax[wn * 64 + row0] = tmax0;
            rMax[wn * 64 + row1] = tmax1;
        }
        __syncthreads();
        float mn0 = fmaxf(m0, fmaxf(rMax[row0], rMax[64 + row0]));
        float mn1 = fmaxf(m1, fmaxf(rMax[row1], rMax[64 + row1]));
        float alpha0 = __expf(m0 - mn0), alpha1 = __expf(m1 - mn1);

        float ps0 = 0.f, ps1 = 0.f;
#pragma unroll
        for (int ni = 0; ni < 4; ni++) {
            int colb = 32 * wn + 8 * ni + 2 * c;
            float p0 = __expf(s[ni][0] - mn0);
            float p1 = __expf(s[ni][1] - mn0);
            float p2 = __expf(s[ni][2] - mn1);
            float p3 = __expf(s[ni][3] - mn1);
            ps0 += p0 + p1; ps1 += p2 + p3;
            *(__half2*)&sPT[row0 * PT_STRIDE + colb] = __floats2half2_rn(p0, p1);
            *(__half2*)&sPT[row1 * PT_STRIDE + colb] = __floats2half2_rn(p2, p3);
        }
        ps0 += __shfl_xor_sync(0xffffffffu, ps0, 1);
        ps0 += __shfl_xor_sync(0xffffffffu, ps0, 2);
        ps1 += __shfl_xor_sync(0xffffffffu, ps1, 1);
        ps1 += __shfl_xor_sync(0xffffffffu, ps1, 2);
        if (c == 0) {
            rSum[wn * 64 + row0] = ps0;
            rSum[wn * 64 + row1] = ps1;
        }
        __syncthreads();
        l0 = l0 * alpha0 + rSum[row0] + rSum[64 + row0];
        l1 = l1 * alpha1 + rSum[row1] + rSum[64 + row1];
        m0 = mn0; m1 = mn1;

#pragma unroll
        for (int nf = 0; nf < 16; nf++) {
            o[nf][0] *= alpha0; o[nf][1] *= alpha0;
            o[nf][2] *= alpha1; o[nf][3] *= alpha1;
        }

        // ---- PV (fp16 m16n8k16): warp rows 16*wm, out cols 128*wn ----
#pragma unroll
        for (int kf = 0; kf < 4; kf++) {
            const int ko = kf * 16 + 2 * c;
            uint32_t a0 = *(const uint32_t*)&sPT[row0 * PT_STRIDE + ko];
            uint32_t a1 = *(const uint32_t*)&sPT[row1 * PT_STRIDE + ko];
            uint32_t a2 = *(const uint32_t*)&sPT[row0 * PT_STRIDE + ko + 8];
            uint32_t a3 = *(const uint32_t*)&sPT[row1 * PT_STRIDE + ko + 8];
#pragma unroll
            for (int nf = 0; nf < 16; nf++) {
                int col = 128 * wn + 8 * nf + r;
                uint32_t b0 = *(const uint32_t*)&sVT[col * VT_STRIDE + ko];
                uint32_t b1 = *(const uint32_t*)&sVT[col * VT_STRIDE + ko + 8];
                mma_f16(o[nf], a0, a1, a2, a3, b0, b1);
            }
        }
    }

    // ---- write out: [b, s, h*256] ----
    const float inv0 = 1.0f / l0, inv1 = 1.0f / l1;
    const int b = bh >> 3, h = bh & 7;
    const size_t gr0 = ((size_t)b * S_ + qt * 64 + row0) * 2048 + h * 256;
    const size_t gr1 = ((size_t)b * S_ + qt * 64 + row1) * 2048 + h * 256;
#pragma unroll
    for (int nf = 0; nf < 16; nf++) {
        int col = 128 * wn + 8 * nf + 2 * c;
        O[gr0 + col]     = o[nf][0] * inv0;
        O[gr0 + col + 1] = o[nf][1] * inv0;
        O[gr1 + col]     = o[nf][2] * inv1;
        O[gr1 + col + 1] = o[nf][3] * inv1;
    }
}

// ---------------- launch ----------------
extern "C" void kernel_launch(void* const* d_in, const int* in_sizes, int n_in,
                              void* d_out, int out_size)
{
    const float* x         = (const float*)d_in[0];
    const int*   pos       = (const int*)  d_in[1];
    const float* w_dq_w    = (const float*)d_in[2];
    const float* w_dq_b    = (const float*)d_in[3];
    const float* q_norm_w  = (const float*)d_in[4];
    const float* w_uq_w    = (const float*)d_in[5];
    const float* w_uq_b    = (const float*)d_in[6];
    const float* w_dkv_w   = (const float*)d_in[7];
    const float* w_dkv_b   = (const float*)d_in[8];
    const float* kv_norm_w = (const float*)d_in[9];
    const float* w_ukv_w   = (const float*)d_in[10];
    const float* w_ukv_b   = (const float*)d_in[11];
    const float* w_o_w     = (const float*)d_in[12];
    const float* w_o_b     = (const float*)d_in[13];
    float* out = (float*)d_out;

    float *cq, *ckv, *q, *kv, *Qs, *Ks, *Vs, *attn;
    cudaGetSymbolAddress((void**)&cq,   g_cq);
    cudaGetSymbolAddress((void**)&ckv,  g_ckv);
    cudaGetSymbolAddress((void**)&q,    g_q);
    cudaGetSymbolAddress((void**)&kv,   g_kv);
    cudaGetSymbolAddress((void**)&Qs,   g_Qs);
    cudaGetSymbolAddress((void**)&Ks,   g_Ks);
    cudaGetSymbolAddress((void**)&Vs,   g_Vs);
    cudaGetSymbolAddress((void**)&attn, g_attn);

    const int M = MROWS;

    // fused fp32 down-projections
    down_proj_fused<<<dim3(5, 32), 256>>>(x, w_dq_w, w_dq_b, w_dkv_w, w_dkv_b, cq, ckv);

    rmsnorm_kernel<<<M, 128>>>(cq,  q_norm_w,  128);
    rmsnorm_kernel<<<M, 128>>>(ckv, kv_norm_w, 192);
    rope_kernel<<<M, 32>>>(ckv, pos, 192, 128, 64);

    // up-projections (tf32 tensor cores)
    gemm_tf32<<<dim3(8, 32), 256>>>(cq,  w_uq_w,  w_uq_b,  q,  M, 1024, 128, 128);
    rope_kernel<<<M, 128>>>(q, pos, 1024, 768, 32);
    gemm_tf32<<<dim3(20, 32), 256>>>(ckv, w_ukv_w, w_ukv_b, kv, M, 2560, 128, 192);

    repack_kernel<<<B_ * NH_ * S_, 128>>>(q, kv, ckv, Qs, Ks, Vs);

    // attention (tf32 QK, fp16 PV)
    cudaFuncSetAttribute(flash_tf32, cudaFuncAttributeMaxDynamicSharedMemorySize, FLASH_SMEM);
    flash_tf32<<<dim3(S_ / 64, B_ * NH_), 256, FLASH_SMEM>>>(Qs, Ks, Vs, attn);

    // output projection (tf32)
    gemm_tf32<<<dim3(8, 32), 256>>>(attn, w_o_w, w_o_b, out, M, 1024, 2048, 2048);
}

// round 16
// speedup vs baseline: 3.1251x; 1.2166x over previous
#include <cuda_runtime.h>
#include <cuda_fp16.h>
#include <cstdint>

#define B_   2
#define S_   2048
#define DIM_ 1024
#define NH_  8
#define MROWS (B_*S_)           // 4096
#define QD   128
#define VD   256

// ---------------- scratch ----------------
__device__ float  g_cq  [MROWS*128];
__device__ float  g_ckv [MROWS*192];
__device__ float  g_q   [MROWS*1024];
__device__ float  g_kv  [(size_t)MROWS*2560];
__device__ float  g_attn[(size_t)MROWS*2048];
__device__ __half g_Qs  [(size_t)B_*NH_*S_*QD];
__device__ __half g_Ks  [(size_t)B_*NH_*S_*QD];
__device__ __half g_Vs  [(size_t)B_*NH_*S_*VD];
__device__ __half g_wuqT [(size_t)1024*128];
__device__ __half g_wukvT[(size_t)2560*128];
__device__ __half g_woT  [(size_t)1024*2048];

// ---------------- helpers ----------------
__device__ __forceinline__ void mma_f16(float* d,
                                        uint32_t a0, uint32_t a1, uint32_t a2, uint32_t a3,
                                        uint32_t b0, uint32_t b1)
{
    asm volatile(
        "mma.sync.aligned.m16n8k16.row.col.f32.f16.f16.f32 "
        "{%0,%1,%2,%3},{%4,%5,%6,%7},{%8,%9},{%0,%1,%2,%3};\n"
        : "+f"(d[0]), "+f"(d[1]), "+f"(d[2]), "+f"(d[3])
        : "r"(a0), "r"(a1), "r"(a2), "r"(a3), "r"(b0), "r"(b1));
}

// ---------------- weight transpose + fp16 convert: src[K,N] f32 -> dst[N,K] f16 ----------------
__global__ void __launch_bounds__(256) w2hT(const float* __restrict__ src,
                                            __half* __restrict__ dst, int K, int N)
{
    __shared__ float t[32][33];
    const int n0 = blockIdx.x * 32, k0 = blockIdx.y * 32;
    const int tx = threadIdx.x & 31, ty = threadIdx.x >> 5;
#pragma unroll
    for (int i = ty; i < 32; i += 8)
        t[i][tx] = src[(size_t)(k0 + i) * N + n0 + tx];
    __syncthreads();
#pragma unroll
    for (int i = ty; i < 32; i += 8)
        dst[(size_t)(n0 + i) * K + k0 + tx] = __float2half(t[tx][i]);
}

// ---------------- fused fp32 down-projections: cq (N=128) + ckv (N=192) ----------------
__global__ void __launch_bounds__(256) down_proj_fused(
    const float* __restrict__ x,
    const float* __restrict__ w_dq,  const float* __restrict__ b_dq,
    const float* __restrict__ w_dkv, const float* __restrict__ b_dkv,
    float* __restrict__ cq, float* __restrict__ ckv)
{
    __shared__ float As[8][128];
    __shared__ float Bs[8][64];

    const int bx = blockIdx.x;
    const float* Bm; const float* bias; float* C; int N, bn;
    if (bx < 2) { Bm = w_dq;  bias = b_dq;  C = cq;  N = 128; bn = bx * 64; }
    else        { Bm = w_dkv; bias = b_dkv; C = ckv; N = 192; bn = (bx - 2) * 64; }

    const int tid = threadIdx.x;
    const int tx  = tid & 15;
    const int ty  = tid >> 4;
    const int bm  = blockIdx.y * 128;

    const int arow = tid >> 1, acol = (tid & 1) << 2;
    const int brow = tid >> 4, bcol = (tid & 15) << 2;

    float acc[8][4];
#pragma unroll
    for (int i = 0; i < 8; i++)
#pragma unroll
        for (int j = 0; j < 4; j++) acc[i][j] = 0.f;

    for (int k0 = 0; k0 < 1024; k0 += 8) {
        float4 av = *(const float4*)&x[(size_t)(bm + arow) * 1024 + k0 + acol];
        float4 bv = make_float4(0.f, 0.f, 0.f, 0.f);
        if (tid < 128)
            bv = *(const float4*)&Bm[(size_t)(k0 + brow) * N + bn + bcol];

        __syncthreads();
        As[acol + 0][arow] = av.x;
        As[acol + 1][arow] = av.y;
        As[acol + 2][arow] = av.z;
        As[acol + 3][arow] = av.w;
        if (tid < 128)
            *(float4*)&Bs[brow][bcol] = bv;
        __syncthreads();

#pragma unroll
        for (int kk = 0; kk < 8; kk++) {
            float4 a0 = *(const float4*)&As[kk][ty * 4];
            float4 a1 = *(const float4*)&As[kk][64 + ty * 4];
            float4 b0 = *(const float4*)&Bs[kk][tx * 4];
            float a[8] = {a0.x, a0.y, a0.z, a0.w, a1.x, a1.y, a1.z, a1.w};
            float b[4] = {b0.x, b0.y, b0.z, b0.w};
#pragma unroll
            for (int i = 0; i < 8; i++)
#pragma unroll
                for (int j = 0; j < 4; j++)
                    acc[i][j] += a[i] * b[j];
        }
    }

#pragma unroll
    for (int i = 0; i < 8; i++) {
        int row = bm + ((i < 4) ? (ty * 4 + i) : (64 + ty * 4 + i - 4));
#pragma unroll
        for (int j = 0; j < 4; j++) {
            int col = bn + tx * 4 + j;
            C[(size_t)row * N + col] = acc[i][j] + bias[col];
        }
    }
}

// ---------------- fp16 tensor-core GEMM: C[M,N] = A[M,K(lda)] @ BT[N,K]^T + bias ----------------
// 128x128 tile, BK=32, 8 warps 2(m)x4(n), warp 64x32. A f32->f16 at store; BT already f16.
__global__ void __launch_bounds__(256) gemm_f16(
    const float* __restrict__ A, const __half* __restrict__ BT,
    const float* __restrict__ bias, float* __restrict__ C,
    int M, int N, int K, int lda)
{
    __shared__ __half As[128 * 40];   // [row*40 + k]
    __shared__ __half Bs[128 * 40];   // [n*40 + k]

    const int tid  = threadIdx.x;
    const int wid  = tid >> 5;
    const int lane = tid & 31;
    const int bm   = blockIdx.y * 128;
    const int bn   = blockIdx.x * 128;
    const int wm   = (wid >> 2) * 64;
    const int wn   = (wid & 3) * 32;
    const int r    = lane >> 2;
    const int c    = lane & 3;

    float acc[4][4][4];
#pragma unroll
    for (int i = 0; i < 4; i++)
#pragma unroll
        for (int j = 0; j < 4; j++)
#pragma unroll
            for (int k = 0; k < 4; k++) acc[i][j][k] = 0.f;

    const int ar = tid >> 1, ac = (tid & 1) << 4;   // A: row, 16 cols at ac
    const int nr = tid >> 1, nc = (tid & 1) << 4;   // BT: n-row, 16 k at nc

    for (int k0 = 0; k0 < K; k0 += 32) {
        const float* ga = &A[(size_t)(bm + ar) * lda + k0 + ac];
        float4 v0 = *(const float4*)(ga);
        float4 v1 = *(const float4*)(ga + 4);
        float4 v2 = *(const float4*)(ga + 8);
        float4 v3 = *(const float4*)(ga + 12);
        const __half* gb = &BT[(size_t)(bn + nr) * K + k0 + nc];
        uint4 u0 = *(const uint4*)(gb);
        uint4 u1 = *(const uint4*)(gb + 8);

        __syncthreads();
        __half* as = &As[ar * 40 + ac];
        *(__half2*)(as + 0)  = __floats2half2_rn(v0.x, v0.y);
        *(__half2*)(as + 2)  = __floats2half2_rn(v0.z, v0.w);
        *(__half2*)(as + 4)  = __floats2half2_rn(v1.x, v1.y);
        *(__half2*)(as + 6)  = __floats2half2_rn(v1.z, v1.w);
        *(__half2*)(as + 8)  = __floats2half2_rn(v2.x, v2.y);
        *(__half2*)(as + 10) = __floats2half2_rn(v2.z, v2.w);
        *(__half2*)(as + 12) = __floats2half2_rn(v3.x, v3.y);
        *(__half2*)(as + 14) = __floats2half2_rn(v3.z, v3.w);
        *(uint4*)&Bs[nr * 40 + nc]     = u0;
        *(uint4*)&Bs[nr * 40 + nc + 8] = u1;
        __syncthreads();

#pragma unroll
        for (int ks = 0; ks < 32; ks += 16) {
            uint32_t a[4][4], b[4][2];
#pragma unroll
            for (int mi = 0; mi < 4; mi++) {
                int row = wm + 16 * mi;
                a[mi][0] = *(const uint32_t*)&As[(row + r) * 40 + ks + 2 * c];
                a[mi][1] = *(const uint32_t*)&As[(row + r + 8) * 40 + ks + 2 * c];
                a[mi][2] = *(const uint32_t*)&As[(row + r) * 40 + ks + 2 * c + 8];
                a[mi][3] = *(const uint32_t*)&As[(row + r + 8) * 40 + ks + 2 * c + 8];
            }
#pragma unroll
            for (int ni = 0; ni < 4; ni++) {
                int coln = wn + 8 * ni + r;
                b[ni][0] = *(const uint32_t*)&Bs[coln * 40 + ks + 2 * c];
                b[ni][1] = *(const uint32_t*)&Bs[coln * 40 + ks + 2 * c + 8];
            }
#pragma unroll
            for (int mi = 0; mi < 4; mi++)
#pragma unroll
                for (int ni = 0; ni < 4; ni++)
                    mma_f16(acc[mi][ni], a[mi][0], a[mi][1], a[mi][2], a[mi][3],
                            b[ni][0], b[ni][1]);
        }
    }

#pragma unroll
    for (int mi = 0; mi < 4; mi++) {
        int row0 = bm + wm + 16 * mi + r;
#pragma unroll
        for (int ni = 0; ni < 4; ni++) {
            int col0 = bn + wn + 8 * ni + 2 * c;
            C[(size_t)row0 * N + col0]           = acc[mi][ni][0] + bias[col0];
            C[(size_t)row0 * N + col0 + 1]       = acc[mi][ni][1] + bias[col0 + 1];
            C[(size_t)(row0 + 8) * N + col0]     = acc[mi][ni][2] + bias[col0];
            C[(size_t)(row0 + 8) * N + col0 + 1] = acc[mi][ni][3] + bias[col0 + 1];
        }
    }
}

// ---------------- small kernels ----------------
__global__ void rmsnorm_kernel(float* __restrict__ buf, const float* __restrict__ w,
                               int stride)
{
    const int row = blockIdx.x;
    const int tid = threadIdx.x;
    float v = buf[(size_t)row * stride + tid];
    float s = v * v;
#pragma unroll
    for (int o = 16; o; o >>= 1) s += __shfl_xor_sync(0xffffffffu, s, o);
    __shared__ float ws[4];
    if ((tid & 31) == 0) ws[tid >> 5] = s;
    __syncthreads();
    float tot = ws[0] + ws[1] + ws[2] + ws[3];
    float rr = rsqrtf(tot / (float)blockDim.x + 1e-8f);
    buf[(size_t)row * stride + tid] = w[tid] * v * rr;
}

__global__ void rope_kernel(float* __restrict__ buf, const int* __restrict__ pos,
                            int stride, int col_off, int hd)
{
    const int row = blockIdx.x;
    const int tid = threadIdx.x;
    const int half = hd >> 1;
    const int h = tid / half, i = tid % half;
    float p = (float)pos[row];
    float freq = powf(10000.0f, -2.0f * (float)i / (float)hd);
    float ang = p * freq;
    float sn, cs;
    sincosf(ang, &sn, &cs);
    size_t base = (size_t)row * stride + col_off + h * hd + 2 * i;
    float xe = buf[base], xo = buf[base + 1];
    buf[base]     = xe * cs - xo * sn;
    buf[base + 1] = xe * sn + xo * cs;
}

// repack into [b,h,s,d] fp16; Q pre-scaled by 1/sqrt(128)
__global__ void repack_kernel(const float* __restrict__ q, const float* __restrict__ kv,
                              const float* __restrict__ ckv,
                              __half* __restrict__ Qo, __half* __restrict__ Ko,
                              __half* __restrict__ Vo)
{
    const int bhs = blockIdx.x;
    const int d   = threadIdx.x;
    const int s   = bhs & (S_ - 1);
    const int bh  = bhs >> 11;
    const int h   = bh & 7;
    const int b   = bh >> 3;
    const size_t row = (size_t)b * S_ + s;
    const size_t o128 = (size_t)bhs * 128, o256 = (size_t)bhs * 256;
    const float scale = 0.08838834764831845f;

    float qv = (d < 96) ? q[row * 1024 + h * 96 + d]
                        : q[row * 1024 + 768 + h * 32 + (d - 96)];
    Qo[o128 + d] = __float2half(qv * scale);
    Ko[o128 + d] = __float2half((d < 64) ? kv[row * 2560 + h * 64 + d]
                                         : ckv[row * 192 + 128 + (d - 64)]);
    Vo[o256 + d]       = __float2half(kv[row * 2560 + 512 + (size_t)h * 256 + d]);
    Vo[o256 + 128 + d] = __float2half(kv[row * 2560 + 512 + (size_t)h * 256 + 128 + d]);
}

// ---------------- flash attention: fp16 QK^T + fp16 PV, fp32 softmax ----------------
// smem (halves): sQ 64x136 | sK 64x136 | sVT 256x72 | sPT 64x72 | rMax(128f) rSum(128f)
// tail needs 2*128 floats = 1024 bytes (this was 512 in R15 -> OOB crash).
#define SQH_STRIDE 136
#define VT_STRIDE  72
#define PT_STRIDE  72
#define FLASH_SMEM ((64*136 + 64*136 + 256*72 + 64*72) * 2 + 1024)

__global__ void __launch_bounds__(256, 2) flash_f16(
    const __half* __restrict__ Q, const __half* __restrict__ K,
    const __half* __restrict__ V, float* __restrict__ O)
{
    extern __shared__ __half smh[];
    __half* sQ  = smh;                      // 64*136
    __half* sK  = sQ + 64 * SQH_STRIDE;     // 64*136
    __half* sVT = sK + 64 * SQH_STRIDE;     // 256*72
    __half* sPT = sVT + 256 * VT_STRIDE;    // 64*72
    float* rMax = (float*)(sPT + 64 * PT_STRIDE);   // 128 floats
    float* rSum = rMax + 128;                       // 128 floats

    const int tid  = threadIdx.x;
    const int wid  = tid >> 5;
    const int lane = tid & 31;
    const int wm   = wid >> 1;
    const int wn   = wid & 1;
    const int r    = lane >> 2;
    const int c    = lane & 3;
    const int bh   = blockIdx.y;
    const int qt   = blockIdx.x;

    // Q tile (fp16, pre-scaled)
    const __half* Qg = Q + ((size_t)bh * S_ + qt * 64) * QD;
    for (int i = tid; i < 64 * 16; i += 256) {
        int row = i >> 4, c8 = (i & 15) << 3;
        *(uint4*)&sQ[row * SQH_STRIDE + c8] = *(const uint4*)&Qg[row * QD + c8];
    }

    float o[16][4];
#pragma unroll
    for (int i = 0; i < 16; i++)
#pragma unroll
        for (int j = 0; j < 4; j++) o[i][j] = 0.f;
    float m0 = -1e30f, m1 = -1e30f, l0 = 0.f, l1 = 0.f;

    const int row0 = 16 * wm + r;
    const int row1 = row0 + 8;

    for (int kt = 0; kt < S_ / 64; kt++) {
        __syncthreads();
        // K tile
        const __half* Kg = K + ((size_t)bh * S_ + kt * 64) * QD;
        for (int i = tid; i < 64 * 16; i += 256) {
            int row = i >> 4, c8 = (i & 15) << 3;
            *(uint4*)&sK[row * SQH_STRIDE + c8] = *(const uint4*)&Kg[row * QD + c8];
        }
        // V tile -> transposed: sVT[col][k], thread owns col = tid
        {
            const __half* vg = V + ((size_t)bh * S_ + (size_t)kt * 64) * VD + tid;
            __half* vd = sVT + tid * VT_STRIDE;
#pragma unroll
            for (int g = 0; g < 16; g++) {
                __half2 lo = __halves2half2(vg[(4 * g + 0) * VD], vg[(4 * g + 1) * VD]);
                __half2 hi = __halves2half2(vg[(4 * g + 2) * VD], vg[(4 * g + 3) * VD]);
                uint2 pk;
                pk.x = *(uint32_t*)&lo;
                pk.y = *(uint32_t*)&hi;
                *(uint2*)&vd[4 * g] = pk;
            }
        }
        __syncthreads();

        // ---- S = Q @ K^T (fp16 m16n8k16, warp: 16 rows x 32 keys) ----
        float s[4][4];
#pragma unroll
        for (int ni = 0; ni < 4; ni++)
#pragma unroll
            for (int j = 0; j < 4; j++) s[ni][j] = 0.f;

#pragma unroll
        for (int ko = 0; ko < 128; ko += 16) {
            uint32_t a0 = *(const uint32_t*)&sQ[row0 * SQH_STRIDE + ko + 2 * c];
            uint32_t a1 = *(const uint32_t*)&sQ[row1 * SQH_STRIDE + ko + 2 * c];
            uint32_t a2 = *(const uint32_t*)&sQ[row0 * SQH_STRIDE + ko + 2 * c + 8];
            uint32_t a3 = *(const uint32_t*)&sQ[row1 * SQH_STRIDE + ko + 2 * c + 8];
#pragma unroll
            for (int ni = 0; ni < 4; ni++) {
                int key = 32 * wn + 8 * ni + r;
                uint32_t b0 = *(const uint32_t*)&sK[key * SQH_STRIDE + ko + 2 * c];
                uint32_t b1 = *(const uint32_t*)&sK[key * SQH_STRIDE + ko + 2 * c + 8];
                mma_f16(s[ni], a0, a1, a2, a3, b0, b1);
            }
        }

        // ---- online softmax (fp32) ----
        float tmax0 = -1e30f, tmax1 = -1e30f;
#pragma unroll
        for (int ni = 0; ni < 4; ni++) {
            tmax0 = fmaxf(tmax0, fmaxf(s[ni][0], s[ni][1]));
            tmax1 = fmaxf(tmax1, fmaxf(s[ni][2], s[ni][3]));
        }
        tmax0 = fmaxf(tmax0, __shfl_xor_sync(0xffffffffu, tmax0, 1));
        tmax0 = fmaxf(tmax0, __shfl_xor_sync(0xffffffffu, tmax0, 2));
        tmax1 = fmaxf(tmax1, __shfl_xor_sync(0xffffffffu, tmax1, 1));
        tmax1 = fmaxf(tmax1, __shfl_xor_sync(0xffffffffu, tmax1, 2));
        if (c == 0) {
            rMax[wn * 64 + row0] = tmax0;
            rMax[wn * 64 + row1] = tmax1;
        }
        __syncthreads();
        float mn0 = fmaxf(m0, fmaxf(rMax[row0], rMax[64 + row0]));
        float mn1 = fmaxf(m1, fmaxf(rMax[row1], rMax[64 + row1]));
        float alpha0 = __expf(m0 - mn0), alpha1 = __expf(m1 - mn1);

        float ps0 = 0.f, ps1 = 0.f;
#pragma unroll
        for (int ni = 0; ni < 4; ni++) {
            int colb = 32 * wn + 8 * ni + 2 * c;
            float p0 = __expf(s[ni][0] - mn0);
            float p1 = __expf(s[ni][1] - mn0);
            float p2 = __expf(s[ni][2] - mn1);
            float p3 = __expf(s[ni][3] - mn1);
            ps0 += p0 + p1; ps1 += p2 + p3;
            *(__half2*)&sPT[row0 * PT_STRIDE + colb] = __floats2half2_rn(p0, p1);
            *(__half2*)&sPT[row1 * PT_STRIDE + colb] = __floats2half2_rn(p2, p3);
        }
        ps0 += __shfl_xor_sync(0xffffffffu, ps0, 1);
        ps0 += __shfl_xor_sync(0xffffffffu, ps0, 2);
        ps1 += __shfl_xor_sync(0xffffffffu, ps1, 1);
        ps1 += __shfl_xor_sync(0xffffffffu, ps1, 2);
        if (c == 0) {
            rSum[wn * 64 + row0] = ps0;
            rSum[wn * 64 + row1] = ps1;
        }
        __syncthreads();
        l0 = l0 * alpha0 + rSum[row0] + rSum[64 + row0];
        l1 = l1 * alpha1 + rSum[row1] + rSum[64 + row1];
        m0 = mn0; m1 = mn1;

#pragma unroll
        for (int nf = 0; nf < 16; nf++) {
            o[nf][0] *= alpha0; o[nf][1] *= alpha0;
            o[nf][2] *= alpha1; o[nf][3] *= alpha1;
        }

        // ---- PV (fp16 m16n8k16): warp rows 16*wm, out cols 128*wn ----
#pragma unroll
        for (int kf = 0; kf < 4; kf++) {
            const int ko = kf * 16 + 2 * c;
            uint32_t a0 = *(const uint32_t*)&sPT[row0 * PT_STRIDE + ko];
            uint32_t a1 = *(const uint32_t*)&sPT[row1 * PT_STRIDE + ko];
            uint32_t a2 = *(const uint32_t*)&sPT[row0 * PT_STRIDE + ko + 8];
            uint32_t a3 = *(const uint32_t*)&sPT[row1 * PT_STRIDE + ko + 8];
#pragma unroll
            for (int nf = 0; nf < 16; nf++) {
                int col = 128 * wn + 8 * nf + r;
                uint32_t b0 = *(const uint32_t*)&sVT[col * VT_STRIDE + ko];
                uint32_t b1 = *(const uint32_t*)&sVT[col * VT_STRIDE + ko + 8];
                mma_f16(o[nf], a0, a1, a2, a3, b0, b1);
            }
        }
    }

    // ---- write out: [b, s, h*256] ----
    const float inv0 = 1.0f / l0, inv1 = 1.0f / l1;
    const int b = bh >> 3, h = bh & 7;
    const size_t gr0 = ((size_t)b * S_ + qt * 64 + row0) * 2048 + h * 256;
    const size_t gr1 = ((size_t)b * S_ + qt * 64 + row1) * 2048 + h * 256;
#pragma unroll
    for (int nf = 0; nf < 16; nf++) {
        int col = 128 * wn + 8 * nf + 2 * c;
        O[gr0 + col]     = o[nf][0] * inv0;
        O[gr0 + col + 1] = o[nf][1] * inv0;
        O[gr1 + col]     = o[nf][2] * inv1;
        O[gr1 + col + 1] = o[nf][3] * inv1;
    }
}

// ---------------- launch ----------------
extern "C" void kernel_launch(void* const* d_in, const int* in_sizes, int n_in,
                              void* d_out, int out_size)
{
    const float* x         = (const float*)d_in[0];
    const int*   pos       = (const int*)  d_in[1];
    const float* w_dq_w    = (const float*)d_in[2];
    const float* w_dq_b    = (const float*)d_in[3];
    const float* q_norm_w  = (const float*)d_in[4];
    const float* w_uq_w    = (const float*)d_in[5];
    const float* w_uq_b    = (const float*)d_in[6];
    const float* w_dkv_w   = (const float*)d_in[7];
    const float* w_dkv_b   = (const float*)d_in[8];
    const float* kv_norm_w = (const float*)d_in[9];
    const float* w_ukv_w   = (const float*)d_in[10];
    const float* w_ukv_b   = (const float*)d_in[11];
    const float* w_o_w     = (const float*)d_in[12];
    const float* w_o_b     = (const float*)d_in[13];
    float* out = (float*)d_out;

    float *cq, *ckv, *q, *kv, *attn;
    __half *Qs, *Ks, *Vs, *wuqT, *wukvT, *woT;
    cudaGetSymbolAddress((void**)&cq,    g_cq);
    cudaGetSymbolAddress((void**)&ckv,   g_ckv);
    cudaGetSymbolAddress((void**)&q,     g_q);
    cudaGetSymbolAddress((void**)&kv,    g_kv);
    cudaGetSymbolAddress((void**)&attn,  g_attn);
    cudaGetSymbolAddress((void**)&Qs,    g_Qs);
    cudaGetSymbolAddress((void**)&Ks,    g_Ks);
    cudaGetSymbolAddress((void**)&Vs,    g_Vs);
    cudaGetSymbolAddress((void**)&wuqT,  g_wuqT);
    cudaGetSymbolAddress((void**)&wukvT, g_wukvT);
    cudaGetSymbolAddress((void**)&woT,   g_woT);

    const int M = MROWS;

    // weight prep: fp16 transposed [N,K]
    w2hT<<<dim3(1024 / 32, 128 / 32), 256>>>(w_uq_w,  wuqT,  128, 1024);
    w2hT<<<dim3(2560 / 32, 128 / 32), 256>>>(w_ukv_w, wukvT, 128, 2560);
    w2hT<<<dim3(1024 / 32, 2048 / 32), 256>>>(w_o_w,  woT,   2048, 1024);

    // fused fp32 down-projections
    down_proj_fused<<<dim3(5, 32), 256>>>(x, w_dq_w, w_dq_b, w_dkv_w, w_dkv_b, cq, ckv);

    rmsnorm_kernel<<<M, 128>>>(cq,  q_norm_w,  128);
    rmsnorm_kernel<<<M, 128>>>(ckv, kv_norm_w, 192);
    rope_kernel<<<M, 32>>>(ckv, pos, 192, 128, 64);

    // up-projections (fp16 tensor cores)
    gemm_f16<<<dim3(8, 32), 256>>>(cq,  wuqT,  w_uq_b,  q,  M, 1024, 128, 128);
    rope_kernel<<<M, 128>>>(q, pos, 1024, 768, 32);
    gemm_f16<<<dim3(20, 32), 256>>>(ckv, wukvT, w_ukv_b, kv, M, 2560, 128, 192);

    repack_kernel<<<B_ * NH_ * S_, 128>>>(q, kv, ckv, Qs, Ks, Vs);

    // attention (fp16 QK + PV, fp32 softmax)
    cudaFuncSetAttribute(flash_f16, cudaFuncAttributeMaxDynamicSharedMemorySize, FLASH_SMEM);
    flash_f16<<<dim3(S_ / 64, B_ * NH_), 256, FLASH_SMEM>>>(Qs, Ks, Vs, attn);

    // output projection (fp16)
    gemm_f16<<<dim3(8, 32), 256>>>(attn, woT, w_o_b, out, M, 1024, 2048, 2048);
}